// round 6
// baseline (speedup 1.0000x reference)
#include <cuda_runtime.h>
#include <cuda_bf16.h>
#include <cuda_fp16.h>
#include <math.h>
#include <stdint.h>
#include <float.h>

#define BSZ   8192
#define MDIM  128
#define NDIM  128
#define KDIM  256
#define MN    16384

// -------- device scratch (no allocations allowed) --------
__device__ float g_wsq[MN];
__device__ float g_pxT[MDIM * BSZ];    // [m][b]
__device__ float g_pyT[NDIM * BSZ];    // [n][b]
__device__ float g_sched[2];           // [0] = d = 2*sigma^2, [1] = lr
__device__ __nv_bfloat16 g_xthi[KDIM * BSZ];  // X^T hi (bf16) [d][b]  (numer)
__device__ __nv_bfloat16 g_xtlo[KDIM * BSZ];  // X^T lo (bf16) [d][b]  (numer)
__device__ __align__(16) __half g_whi[MN * KDIM];   // W hi (fp16) [j][k]
__device__ __align__(16) __half g_wlo[MN * KDIM];   // W lo
__device__ __align__(16) __half g_xhi[BSZ * KDIM];  // X hi (fp16) [b][k]
__device__ __align__(16) __half g_xlo[BSZ * KDIM];  // X lo
__device__ float g_pz[2 * BSZ];        // partial argmin value per (half, b)
__device__ int   g_pj[2 * BSZ];        // partial argmin index (global j)

// single shared dynamic-smem symbol for all kernels in this TU
extern __shared__ float sm[];

__device__ __forceinline__ uint32_t smem_u32(const void* p) {
    uint32_t a;
    asm("{ .reg .u64 t; cvta.to.shared.u64 t, %1; cvt.u32.u64 %0, t; }"
        : "=r"(a) : "l"(p));
    return a;
}
__device__ __forceinline__ uint32_t pk2(__nv_bfloat16 a, __nv_bfloat16 b) {
    __nv_bfloat162 t = __halves2bfloat162(a, b);
    return *reinterpret_cast<uint32_t*>(&t);
}

// m16n8k16 HMMA fp32 accumulate (base-target PTX)
__device__ __forceinline__ void mma_bf16(float* d,
                                         uint32_t a0, uint32_t a1,
                                         uint32_t a2, uint32_t a3,
                                         uint32_t b0, uint32_t b1) {
    asm volatile(
        "mma.sync.aligned.m16n8k16.row.col.f32.bf16.bf16.f32 "
        "{%0,%1,%2,%3}, {%4,%5,%6,%7}, {%8,%9}, {%0,%1,%2,%3};"
        : "+f"(d[0]), "+f"(d[1]), "+f"(d[2]), "+f"(d[3])
        : "r"(a0), "r"(a1), "r"(a2), "r"(a3), "r"(b0), "r"(b1));
}
__device__ __forceinline__ void mma_f16(float* d,
                                        uint32_t a0, uint32_t a1,
                                        uint32_t a2, uint32_t a3,
                                        uint32_t b0, uint32_t b1) {
    asm volatile(
        "mma.sync.aligned.m16n8k16.row.col.f32.f16.f16.f32 "
        "{%0,%1,%2,%3}, {%4,%5,%6,%7}, {%8,%9}, {%0,%1,%2,%3};"
        : "+f"(d[0]), "+f"(d[1]), "+f"(d[2]), "+f"(d[3])
        : "r"(a0), "r"(a1), "r"(a2), "r"(a3), "r"(b0), "r"(b1));
}

__device__ __forceinline__ void cpa16(uint32_t saddr, const void* g) {
    asm volatile("cp.async.cg.shared.global [%0], [%1], 16;"
                 :: "r"(saddr), "l"(g));
}
#define CPA_COMMIT() asm volatile("cp.async.commit_group;" ::: "memory")
#define CPA_WAIT1()  asm volatile("cp.async.wait_group 1;" ::: "memory")
#define CPA_WAIT0()  asm volatile("cp.async.wait_group 0;" ::: "memory")

// ============================================================
// Kernel 1: wsq (row sums of squares of W) + scalar schedule.
// ============================================================
__global__ void ker_sq(const float* __restrict__ W,
                       const int*  __restrict__ itp) {
    if (blockIdx.x == 0 && threadIdx.x == 0) {
        int it = itp[0];
        double TAU   = 20.0 / log(64.0);
        double sigma = 64.0 * exp(-(double)it / TAU);
        g_sched[0] = (float)(2.0 * sigma * sigma);
        g_sched[1] = (float)(0.5 * exp(-(double)it / 20.0));
    }
    int warp = (blockIdx.x * blockDim.x + threadIdx.x) >> 5;
    int lane = threadIdx.x & 31;
    if (warp >= MN) return;
    const float* src = W + (size_t)warp * KDIM;
    float s = 0.f;
#pragma unroll
    for (int c = lane; c < KDIM; c += 32) { float v = src[c]; s += v * v; }
#pragma unroll
    for (int o = 16; o > 0; o >>= 1) s += __shfl_down_sync(0xffffffffu, s, o);
    if (lane == 0) g_wsq[warp] = s;
}

// ============================================================
// Kernel 1b: fp16 hi/lo row-major splits of W and X (dist inputs)
// ============================================================
#define WPAIRS (MN * KDIM / 2)
#define XPAIRS (BSZ * KDIM / 2)
__global__ void ker_split(const float* __restrict__ W,
                          const float* __restrict__ X) {
    int idx = blockIdx.x * 256 + threadIdx.x;
    const float* src;
    __half *dhi, *dlo;
    int p;
    if (idx < WPAIRS) {
        src = W; dhi = g_whi; dlo = g_wlo; p = idx;
    } else if (idx < WPAIRS + XPAIRS) {
        src = X; dhi = g_xhi; dlo = g_xlo; p = idx - WPAIRS;
    } else return;
    float2 v = *(const float2*)(src + (size_t)p * 2);
    __half h0 = __float2half_rn(v.x);
    __half h1 = __float2half_rn(v.y);
    __half l0 = __float2half_rn(v.x - __half2float(h0));
    __half l1 = __float2half_rn(v.y - __half2float(h1));
    *(__half2*)(dhi + (size_t)p * 2) = __halves2half2(h0, h1);
    *(__half2*)(dlo + (size_t)p * 2) = __halves2half2(l0, l1);
}

// ============================================================
// Kernel 1c: X [b][d] fp32 -> transposed split-bf16 (numer inputs)
// ============================================================
__global__ void ker_prep(const float* __restrict__ X) {
    __shared__ float t[64][65];
    int bt = blockIdx.x;
    int dt = blockIdx.y;
    int tid = threadIdx.x;
#pragma unroll
    for (int s = 0; s < 16; s++) {
        int e = tid + 256 * s;
        int b = e >> 6, d = e & 63;
        t[b][d] = X[(size_t)(bt * 64 + b) * KDIM + dt * 64 + d];
    }
    __syncthreads();
#pragma unroll
    for (int s = 0; s < 8; s++) {
        int p = tid + 256 * s;
        int d = p >> 5, bp = p & 31;
        float a0 = t[bp * 2][d], a1 = t[bp * 2 + 1][d];
        __nv_bfloat16 h0 = __float2bfloat16_rn(a0);
        __nv_bfloat16 h1 = __float2bfloat16_rn(a1);
        __nv_bfloat16 l0 = __float2bfloat16_rn(a0 - __bfloat162float(h0));
        __nv_bfloat16 l1 = __float2bfloat16_rn(a1 - __bfloat162float(h1));
        size_t idx = (size_t)(dt * 64 + d) * BSZ + bt * 64 + bp * 2;
        *(uint32_t*)((char*)g_xthi + idx * 2) = pk2(h0, h1);
        *(uint32_t*)((char*)g_xtlo + idx * 2) = pk2(l0, l1);
    }
}

// ============================================================
// Kernel 2: fused distance GEMM (split-fp16 HMMA) + argmin.
// Retiled: warp = 64 b x 64 j (acc[4][8][4]). W streamed as
// 256 j x 32 k hi/lo chunks, cp.async double-buffered.
// score z = wsq[j] - 2*dot (monotone equiv of reference).
// ============================================================
#define XS_STRIDE 544                       // 256*2 + 32 pad
#define OFF_XHI2  0
#define OFF_XLO2  (128 * XS_STRIDE)         // 69632
#define OFF_WBUF  (2 * 128 * XS_STRIDE)     // 139264
#define WROW      80                        // 32k*2B + 16 pad
#define WLO_OFF   (256 * WROW)              // 20480
#define WBUF_SZ   (2 * 256 * WROW)          // 40960
#define DIST_SMEM (OFF_WBUF + 2 * WBUF_SZ)  // 221184

__device__ __forceinline__ void dist_prefetch(uint32_t sbase, int ci,
                                              int jbase, int tid) {
    int jt = ci >> 3, kc = ci & 7;
    uint32_t dbuf = sbase + OFF_WBUF + (uint32_t)(ci & 1) * WBUF_SZ;
    size_t gro = ((size_t)(jbase + jt * 256)) * KDIM + kc * 32;
#pragma unroll
    for (int t = 0; t < 4; t++) {
        int i = tid + 256 * t;          // 1024 16B segs per operand
        int r = i >> 2, s = i & 3;
        const char* sh = (const char*)(g_whi + gro + (size_t)r * KDIM) + s * 16;
        const char* sl = (const char*)(g_wlo + gro + (size_t)r * KDIM) + s * 16;
        cpa16(dbuf + r * WROW + s * 16, sh);
        cpa16(dbuf + WLO_OFF + r * WROW + s * 16, sl);
    }
}

__global__ void __launch_bounds__(256, 1)
ker_dist_mma() {
    char* base = (char*)sm;
    uint32_t sbase = smem_u32(base);
    const int tid  = threadIdx.x;
    const int lane = tid & 31;
    const int wid  = tid >> 5;
    const int wb   = wid >> 2;        // warp b-group (0..1) -> 64 b each
    const int wj   = wid & 3;         // warp j-group (0..3) -> 64 j each
    const int g    = lane >> 2;
    const int c2   = (lane & 3) * 2;
    const int b0   = blockIdx.x * 128;
    const int half = blockIdx.y;
    const int jbase = half * 8192;

    // ---- load X tile (hi/lo fp16), 128 rows x 512B ----
#pragma unroll
    for (int t = 0; t < 16; t++) {
        int i = tid + 256 * t;
        int r = i >> 5, s = i & 31;
        *(uint4*)(base + OFF_XHI2 + r * XS_STRIDE + s * 16) =
            *(const uint4*)((const char*)(g_xhi + (size_t)(b0 + r) * KDIM) + s * 16);
        *(uint4*)(base + OFF_XLO2 + r * XS_STRIDE + s * 16) =
            *(const uint4*)((const char*)(g_xlo + (size_t)(b0 + r) * KDIM) + s * 16);
    }

    float bz[8];
    int   bj[8];
#pragma unroll
    for (int i = 0; i < 8; i++) { bz[i] = FLT_MAX; bj[i] = 0; }

    dist_prefetch(sbase, 0, jbase, tid);
    CPA_COMMIT();

    float acc[4][8][4];

    for (int ci = 0; ci < 256; ci++) {
        const int jt = ci >> 3, kc = ci & 7;
        if (ci + 1 < 256) dist_prefetch(sbase, ci + 1, jbase, tid);
        CPA_COMMIT();
        CPA_WAIT1();
        __syncthreads();

        if (kc == 0) {
#pragma unroll
            for (int bt = 0; bt < 4; bt++)
#pragma unroll
                for (int nt = 0; nt < 8; nt++)
#pragma unroll
                    for (int r = 0; r < 4; r++) acc[bt][nt][r] = 0.f;
        }

        const uint32_t wboff = OFF_WBUF + (uint32_t)(ci & 1) * WBUF_SZ;
#pragma unroll
        for (int ks = 0; ks < 2; ks++) {
            // B fragments: 8 nt, hi+lo
            const int kbW = (ks * 16 + c2) * 2;
            uint32_t bh[8][2], bl[8][2];
#pragma unroll
            for (int nt = 0; nt < 8; nt++) {
                int ro = (wj * 64 + nt * 8 + g) * WROW + kbW;
                bh[nt][0] = *(const uint32_t*)(base + wboff + ro);
                bh[nt][1] = *(const uint32_t*)(base + wboff + ro + 16);
                bl[nt][0] = *(const uint32_t*)(base + wboff + WLO_OFF + ro);
                bl[nt][1] = *(const uint32_t*)(base + wboff + WLO_OFF + ro + 16);
            }
            const int kbX = (kc * 32 + ks * 16 + c2) * 2;
#pragma unroll
            for (int bt = 0; bt < 4; bt++) {
                int ro = (wb * 64 + bt * 16 + g) * XS_STRIDE + kbX;
                uint32_t a0 = *(const uint32_t*)(base + OFF_XHI2 + ro);
                uint32_t a1 = *(const uint32_t*)(base + OFF_XHI2 + ro + 8 * XS_STRIDE);
                uint32_t a2 = *(const uint32_t*)(base + OFF_XHI2 + ro + 16);
                uint32_t a3 = *(const uint32_t*)(base + OFF_XHI2 + ro + 8 * XS_STRIDE + 16);
                uint32_t l0 = *(const uint32_t*)(base + OFF_XLO2 + ro);
                uint32_t l1 = *(const uint32_t*)(base + OFF_XLO2 + ro + 8 * XS_STRIDE);
                uint32_t l2 = *(const uint32_t*)(base + OFF_XLO2 + ro + 16);
                uint32_t l3 = *(const uint32_t*)(base + OFF_XLO2 + ro + 8 * XS_STRIDE + 16);
#pragma unroll
                for (int nt = 0; nt < 8; nt++) {
                    mma_f16(acc[bt][nt], a0, a1, a2, a3, bh[nt][0], bh[nt][1]);
                    mma_f16(acc[bt][nt], a0, a1, a2, a3, bl[nt][0], bl[nt][1]);
                    mma_f16(acc[bt][nt], l0, l1, l2, l3, bh[nt][0], bh[nt][1]);
                }
            }
        }

        if (kc == 7) {
            const int j0 = jt * 256 + wj * 64;
#pragma unroll
            for (int nt = 0; nt < 8; nt++) {
                int jg = j0 + nt * 8 + c2;
                float w0 = g_wsq[jbase + jg];
                float w1 = g_wsq[jbase + jg + 1];
#pragma unroll
                for (int bt = 0; bt < 4; bt++) {
                    float z00 = fmaf(-2.f, acc[bt][nt][0], w0);
                    float z01 = fmaf(-2.f, acc[bt][nt][1], w1);
                    float z10 = fmaf(-2.f, acc[bt][nt][2], w0);
                    float z11 = fmaf(-2.f, acc[bt][nt][3], w1);
                    int s0 = bt * 2, s1 = bt * 2 + 1;
                    if (z00 < bz[s0]) { bz[s0] = z00; bj[s0] = jg; }
                    if (z01 < bz[s0]) { bz[s0] = z01; bj[s0] = jg + 1; }
                    if (z10 < bz[s1]) { bz[s1] = z10; bj[s1] = jg; }
                    if (z11 < bz[s1]) { bz[s1] = z11; bj[s1] = jg + 1; }
                }
            }
        }
        __syncthreads();
    }

    // ---- cross-lane (c bits) argmin reduction ----
#pragma unroll
    for (int i = 0; i < 8; i++) {
        float z = bz[i]; int j = bj[i];
#pragma unroll
        for (int off = 1; off <= 2; off <<= 1) {
            float oz = __shfl_xor_sync(0xffffffffu, z, off);
            int   oj = __shfl_xor_sync(0xffffffffu, j, off);
            if (oz < z || (oz == z && oj < j)) { z = oz; j = oj; }
        }
        bz[i] = z; bj[i] = j;
    }

    // ---- cross-warp reduction via smem (reuse W buffers) ----
    float* sz = (float*)(base + OFF_WBUF);
    int*   sj = (int*)(base + OFF_WBUF + 2048);
    if ((lane & 3) == 0) {
#pragma unroll
        for (int i = 0; i < 8; i++) {
            int bt = i >> 1, h = i & 1;
            int row = wb * 64 + bt * 16 + g + 8 * h;
            sz[row * 4 + wj] = bz[i];
            sj[row * 4 + wj] = bj[i];
        }
    }
    __syncthreads();
    if (tid < 128) {
        float z = sz[tid * 4]; int j = sj[tid * 4];
#pragma unroll
        for (int t = 1; t < 4; t++) {
            float oz = sz[tid * 4 + t]; int oj = sj[tid * 4 + t];
            if (oz < z || (oz == z && oj < j)) { z = oz; j = oj; }
        }
        g_pz[half * BSZ + b0 + tid] = z;
        g_pj[half * BSZ + b0 + tid] = jbase + j;
    }
}

// ============================================================
// Kernel 3: combine halves -> BMU -> neighborhood factors
// ============================================================
__global__ void ker_pxpy() {
    int i = blockIdx.x;
    float d  = g_sched[0];
    float lr = g_sched[1];
    float fi = (float)i;
    for (int b = threadIdx.x; b < BSZ; b += 256) {
        float z0 = g_pz[b], z1 = g_pz[BSZ + b];
        int bmu = (z1 < z0) ? g_pj[BSZ + b] : g_pj[b];
        float dr = fi - (float)(bmu >> 7);
        float dc = fi - (float)(bmu & 127);
        g_pxT[(size_t)i * BSZ + b] = expf(-(dr * dr) / d);
        g_pyT[(size_t)i * BSZ + b] = lr * expf(-(dc * dc) / d);
    }
}

// ============================================================
// Kernel 4: numer via split-bf16 HMMA (+fused denom), pipelined.
// One CTA per m. D[128 n x 256 d]; K=8192 over b in 256 chunks
// of 32. A (px*py hi/lo) and X^T (hi/lo) double-buffered; X via
// cp.async; A staged (LDG+convert+STS) overlapped with MMAs.
// ============================================================
#define N_ROW   80                           // 32b*2B + 16 pad
#define N_ALO   (128 * N_ROW)                // 10240 (within A buffer)
#define N_ABUF  (2 * 128 * N_ROW)            // 20480
#define N_XLO   (256 * N_ROW)                // 20480 (within X buffer)
#define N_XBUF  (2 * 256 * N_ROW)            // 40960
#define OFF_DSUM 0
#define OFF_A0   512
#define OFF_X0   (OFF_A0 + 2 * N_ABUF)       // 41472
#define NUMER_SMEM (OFF_X0 + 2 * N_XBUF)     // 123392

__global__ void __launch_bounds__(256, 1)
ker_numer_tc(const float* __restrict__ Wold, float* __restrict__ OUT) {
    char* base = (char*)sm;
    uint32_t sbase = smem_u32(base);
    float* dsum = (float*)(base + OFF_DSUM);

    const int tid  = threadIdx.x;
    const int wid  = tid >> 5;
    const int lane = tid & 31;
    const int m    = blockIdx.x;

    const int n0 = (wid >> 2) * 64;
    const int d0 = (wid & 3) * 64;
    const int g  = lane >> 2;
    const int c2 = (lane & 3) * 2;

    if (tid < 128) dsum[tid] = 0.f;

    float acc[4][8][4];
#pragma unroll
    for (int mt = 0; mt < 4; mt++)
#pragma unroll
        for (int nt = 0; nt < 8; nt++)
#pragma unroll
            for (int r = 0; r < 4; r++) acc[mt][nt][r] = 0.f;

    const float* pxm = g_pxT + (size_t)m * BSZ;
    const int bg = tid & 3;            // b-group (8 b) for A staging
    const int nrow = tid >> 2;         // n row base (0..63), +64 for s=1
    float dden[2] = {0.f, 0.f};

    // ---- staging helpers (inline) ----
    //  X prefetch for chunk ch into buffer ch&1 (cp.async)
    //  A stage for chunk ch: LDG px/py -> convert -> STS
#define NUMER_XPREF(ch) do {                                                  \
        int b0c = (ch) * 32;                                                  \
        uint32_t xb = sbase + OFF_X0 + (uint32_t)((ch) & 1) * N_XBUF;         \
        _Pragma("unroll")                                                     \
        for (int t = 0; t < 4; t++) {                                         \
            int i = tid + 256 * t;                                            \
            int r = i >> 2, s = i & 3;                                        \
            size_t go = ((size_t)r * BSZ + b0c + s * 8) * 2;                  \
            cpa16(xb + r * N_ROW + s * 16, (const char*)g_xthi + go);         \
            cpa16(xb + N_XLO + r * N_ROW + s * 16, (const char*)g_xtlo + go); \
        }                                                                     \
    } while (0)

    for (int ch = 0; ch < 256; ch++) {
        const int cur = ch & 1;

        if (ch == 0) {
            NUMER_XPREF(0);
            CPA_COMMIT();
        }
        // prefetch X for next chunk
        if (ch + 1 < 256) {
            NUMER_XPREF(ch + 1);
            CPA_COMMIT();
        }

        // ---- load px/py for A(ch) early (LDG latency overlap) ----
        const int b0c = ch * 32;
        float4 pxq0 = *(const float4*)(pxm + b0c + bg * 8);
        float4 pxq1 = *(const float4*)(pxm + b0c + bg * 8 + 4);
        float4 py0[2], py1[2];
#pragma unroll
        for (int s = 0; s < 2; s++) {
            int n = nrow + 64 * s;
            const float* py = g_pyT + (size_t)n * BSZ + b0c + bg * 8;
            py0[s] = *(const float4*)py;
            py1[s] = *(const float4*)(py + 4);
        }

        // ---- convert + STS A(ch) into buffer cur ----
        {
            uint32_t ab = sbase + OFF_A0 + (uint32_t)cur * N_ABUF;
            float pxv[8] = {pxq0.x, pxq0.y, pxq0.z, pxq0.w,
                            pxq1.x, pxq1.y, pxq1.z, pxq1.w};
#pragma unroll
            for (int s = 0; s < 2; s++) {
                int n = nrow + 64 * s;
                float a[8] = {pxv[0]*py0[s].x, pxv[1]*py0[s].y,
                              pxv[2]*py0[s].z, pxv[3]*py0[s].w,
                              pxv[4]*py1[s].x, pxv[5]*py1[s].y,
                              pxv[6]*py1[s].z, pxv[7]*py1[s].w};
                float ssum = 0.f;
                __nv_bfloat16 h[8], l[8];
#pragma unroll
                for (int j = 0; j < 8; j++) {
                    ssum += a[j];
                    h[j] = __float2bfloat16_rn(a[j]);
                    l[j] = __float2bfloat16_rn(a[j] - __bfloat162float(h[j]));
                }
                dden[s] += ssum;
                uint4 hv = make_uint4(pk2(h[0],h[1]), pk2(h[2],h[3]),
                                      pk2(h[4],h[5]), pk2(h[6],h[7]));
                uint4 lv = make_uint4(pk2(l[0],l[1]), pk2(l[2],l[3]),
                                      pk2(l[4],l[5]), pk2(l[6],l[7]));
                uint32_t so = n * N_ROW + bg * 16;
                *(uint4*)((char*)base + (ab - sbase) + so) = hv;
                *(uint4*)((char*)base + (ab - sbase) + N_ALO + so) = lv;
            }
        }

        // wait for this chunk's X (group containing it has <=1 newer group)
        if (ch + 1 < 256) { CPA_WAIT1(); } else { CPA_WAIT0(); }
        __syncthreads();

        // ---- MMAs for chunk ch ----
        const uint32_t aoff = OFF_A0 + (uint32_t)cur * N_ABUF;
        const uint32_t xoff = OFF_X0 + (uint32_t)cur * N_XBUF;
#pragma unroll
        for (int kk = 0; kk < 2; kk++) {
            const int kb = (kk * 16 + c2) * 2;
            uint32_t bh[8][2], bl[8][2];
#pragma unroll
            for (int nt = 0; nt < 8; nt++) {
                int ro = (d0 + nt * 8 + g) * N_ROW + kb;
                bh[nt][0] = *(const uint32_t*)(base + xoff + ro);
                bh[nt][1] = *(const uint32_t*)(base + xoff + ro + 16);
                bl[nt][0] = *(const uint32_t*)(base + xoff + N_XLO + ro);
                bl[nt][1] = *(const uint32_t*)(base + xoff + N_XLO + ro + 16);
            }
#pragma unroll
            for (int mt = 0; mt < 4; mt++) {
                int ro = (n0 + mt * 16 + g) * N_ROW + kb;
                uint32_t a0 = *(const uint32_t*)(base + aoff + ro);
                uint32_t a1 = *(const uint32_t*)(base + aoff + ro + 8 * N_ROW);
                uint32_t a2 = *(const uint32_t*)(base + aoff + ro + 16);
                uint32_t a3 = *(const uint32_t*)(base + aoff + ro + 8 * N_ROW + 16);
                uint32_t l0 = *(const uint32_t*)(base + aoff + N_ALO + ro);
                uint32_t l1 = *(const uint32_t*)(base + aoff + N_ALO + ro + 8 * N_ROW);
                uint32_t l2 = *(const uint32_t*)(base + aoff + N_ALO + ro + 16);
                uint32_t l3 = *(const uint32_t*)(base + aoff + N_ALO + ro + 8 * N_ROW + 16);
#pragma unroll
                for (int nt = 0; nt < 8; nt++) {
                    mma_bf16(acc[mt][nt], a0, a1, a2, a3, bh[nt][0], bh[nt][1]);
                    mma_bf16(acc[mt][nt], a0, a1, a2, a3, bl[nt][0], bl[nt][1]);
                    mma_bf16(acc[mt][nt], l0, l1, l2, l3, bh[nt][0], bh[nt][1]);
                }
            }
        }
        __syncthreads();   // compute done before buffers ch&1 reused at ch+2
    }

    // ---- denom reduction ----
#pragma unroll
    for (int s = 0; s < 2; s++)
        atomicAdd(&dsum[nrow + 64 * s], dden[s]);
    __syncthreads();

    // ---- epilogue: divide by denom, write ----
#pragma unroll
    for (int mt = 0; mt < 4; mt++) {
#pragma unroll
        for (int gg = 0; gg < 2; gg++) {
            int n = n0 + mt * 16 + g + gg * 8;
            float den = dsum[n];
            size_t rb = ((size_t)(m * 128 + n)) * KDIM;
#pragma unroll
            for (int nt = 0; nt < 8; nt++) {
                int dcol = d0 + nt * 8 + c2;
                float v0 = acc[mt][nt][gg * 2];
                float v1 = acc[mt][nt][gg * 2 + 1];
                float2 o;
                if (den != 0.f) {
                    o.x = v0 / den; o.y = v1 / den;
                } else {
                    o.x = Wold[rb + dcol]; o.y = Wold[rb + dcol + 1];
                }
                *(float2*)(OUT + rb + dcol) = o;
            }
        }
    }
}

// ============================================================
extern "C" void kernel_launch(void* const* d_in, const int* in_sizes, int n_in,
                              void* d_out, int out_size) {
    (void)in_sizes; (void)n_in; (void)out_size;
    const float* data    = (const float*)d_in[0];
    const float* weights = (const float*)d_in[1];
    const int*   itp     = (const int*)d_in[2];
    float*       out     = (float*)d_out;

    cudaFuncSetAttribute(ker_dist_mma, cudaFuncAttributeMaxDynamicSharedMemorySize,
                         DIST_SMEM);
    cudaFuncSetAttribute(ker_numer_tc, cudaFuncAttributeMaxDynamicSharedMemorySize,
                         NUMER_SMEM);

    ker_sq<<<MN / 8, 256>>>(weights, itp);
    ker_split<<<(WPAIRS + XPAIRS) / 256, 256>>>(weights, data);
    ker_prep<<<dim3(BSZ / 64, KDIM / 64), 256>>>(data);
    ker_dist_mma<<<dim3(64, 2), 256, DIST_SMEM>>>();
    ker_pxpy<<<128, 256>>>();
    ker_numer_tc<<<128, 256, NUMER_SMEM>>>(weights, out);
}

// round 7
// speedup vs baseline: 1.1461x; 1.1461x over previous
#include <cuda_runtime.h>
#include <cuda_bf16.h>
#include <cuda_fp16.h>
#include <math.h>
#include <stdint.h>
#include <float.h>

#define BSZ   8192
#define MDIM  128
#define NDIM  128
#define KDIM  256
#define MN    16384

// -------- device scratch --------
__device__ float g_wsq[MN];
__device__ float g_pxT[MDIM * BSZ];    // [m][b]
__device__ float g_pyT[NDIM * BSZ];    // [n][b]
__device__ float g_sched[2];           // [0] = 2*sigma^2, [1] = lr
__device__ __nv_bfloat16 g_xthi[KDIM * BSZ];  // X^T hi (bf16) [d][b]
__device__ __nv_bfloat16 g_xtlo[KDIM * BSZ];  // X^T lo (bf16) [d][b]
__device__ __align__(16) __half g_whi[MN * KDIM];   // W hi (fp16) [j][k]
__device__ __align__(16) __half g_wlo[MN * KDIM];   // W lo
__device__ __align__(16) __half g_xhi[BSZ * KDIM];  // X hi (fp16) [b][k]
__device__ __align__(16) __half g_xlo[BSZ * KDIM];  // X lo
__device__ float g_pz[2 * BSZ];
__device__ int   g_pj[2 * BSZ];

extern __shared__ float sm[];

__device__ __forceinline__ uint32_t smem_u32(const void* p) {
    uint32_t a;
    asm("{ .reg .u64 t; cvta.to.shared.u64 t, %1; cvt.u32.u64 %0, t; }"
        : "=r"(a) : "l"(p));
    return a;
}
__device__ __forceinline__ uint32_t pk2(__nv_bfloat16 a, __nv_bfloat16 b) {
    __nv_bfloat162 t = __halves2bfloat162(a, b);
    return *reinterpret_cast<uint32_t*>(&t);
}
__device__ __forceinline__ void mma_bf16(float* d,
                                         uint32_t a0, uint32_t a1,
                                         uint32_t a2, uint32_t a3,
                                         uint32_t b0, uint32_t b1) {
    asm volatile(
        "mma.sync.aligned.m16n8k16.row.col.f32.bf16.bf16.f32 "
        "{%0,%1,%2,%3}, {%4,%5,%6,%7}, {%8,%9}, {%0,%1,%2,%3};"
        : "+f"(d[0]), "+f"(d[1]), "+f"(d[2]), "+f"(d[3])
        : "r"(a0), "r"(a1), "r"(a2), "r"(a3), "r"(b0), "r"(b1));
}
__device__ __forceinline__ void mma_f16(float* d,
                                        uint32_t a0, uint32_t a1,
                                        uint32_t a2, uint32_t a3,
                                        uint32_t b0, uint32_t b1) {
    asm volatile(
        "mma.sync.aligned.m16n8k16.row.col.f32.f16.f16.f32 "
        "{%0,%1,%2,%3}, {%4,%5,%6,%7}, {%8,%9}, {%0,%1,%2,%3};"
        : "+f"(d[0]), "+f"(d[1]), "+f"(d[2]), "+f"(d[3])
        : "r"(a0), "r"(a1), "r"(a2), "r"(a3), "r"(b0), "r"(b1));
}
__device__ __forceinline__ void ldsm_x4(uint32_t& r0, uint32_t& r1,
                                        uint32_t& r2, uint32_t& r3,
                                        uint32_t addr) {
    asm volatile("ldmatrix.sync.aligned.m8n8.x4.shared.b16 {%0,%1,%2,%3}, [%4];"
                 : "=r"(r0), "=r"(r1), "=r"(r2), "=r"(r3) : "r"(addr));
}
__device__ __forceinline__ void cpa16(uint32_t saddr, const void* g) {
    asm volatile("cp.async.cg.shared.global [%0], [%1], 16;"
                 :: "r"(saddr), "l"(g));
}
#define CPA_COMMIT() asm volatile("cp.async.commit_group;" ::: "memory")
#define CPA_WAIT1()  asm volatile("cp.async.wait_group 1;" ::: "memory")

// ============================================================
// Kernel 1: wsq + schedule
// ============================================================
__global__ void ker_sq(const float* __restrict__ W,
                       const int*  __restrict__ itp) {
    if (blockIdx.x == 0 && threadIdx.x == 0) {
        int it = itp[0];
        double TAU   = 20.0 / log(64.0);
        double sigma = 64.0 * exp(-(double)it / TAU);
        g_sched[0] = (float)(2.0 * sigma * sigma);
        g_sched[1] = (float)(0.5 * exp(-(double)it / 20.0));
    }
    int warp = (blockIdx.x * blockDim.x + threadIdx.x) >> 5;
    int lane = threadIdx.x & 31;
    if (warp >= MN) return;
    const float* src = W + (size_t)warp * KDIM;
    float s = 0.f;
#pragma unroll
    for (int c = lane; c < KDIM; c += 32) { float v = src[c]; s += v * v; }
#pragma unroll
    for (int o = 16; o > 0; o >>= 1) s += __shfl_down_sync(0xffffffffu, s, o);
    if (lane == 0) g_wsq[warp] = s;
}

// ============================================================
// Kernel 1b: fp16 hi/lo splits of W and X (dist inputs)
// ============================================================
#define WPAIRS (MN * KDIM / 2)
#define XPAIRS (BSZ * KDIM / 2)
__global__ void ker_split(const float* __restrict__ W,
                          const float* __restrict__ X) {
    int idx = blockIdx.x * 256 + threadIdx.x;
    const float* src;
    __half *dhi, *dlo;
    int p;
    if (idx < WPAIRS) {
        src = W; dhi = g_whi; dlo = g_wlo; p = idx;
    } else if (idx < WPAIRS + XPAIRS) {
        src = X; dhi = g_xhi; dlo = g_xlo; p = idx - WPAIRS;
    } else return;
    float2 v = *(const float2*)(src + (size_t)p * 2);
    __half h0 = __float2half_rn(v.x);
    __half h1 = __float2half_rn(v.y);
    __half l0 = __float2half_rn(v.x - __half2float(h0));
    __half l1 = __float2half_rn(v.y - __half2float(h1));
    *(__half2*)(dhi + (size_t)p * 2) = __halves2half2(h0, h1);
    *(__half2*)(dlo + (size_t)p * 2) = __halves2half2(l0, l1);
}

// ============================================================
// Kernel 1c: X -> transposed split-bf16 (numer inputs)
// ============================================================
__global__ void ker_prep(const float* __restrict__ X) {
    __shared__ float t[64][65];
    int bt = blockIdx.x;
    int dt = blockIdx.y;
    int tid = threadIdx.x;
#pragma unroll
    for (int s = 0; s < 16; s++) {
        int e = tid + 256 * s;
        int b = e >> 6, d = e & 63;
        t[b][d] = X[(size_t)(bt * 64 + b) * KDIM + dt * 64 + d];
    }
    __syncthreads();
#pragma unroll
    for (int s = 0; s < 8; s++) {
        int p = tid + 256 * s;
        int d = p >> 5, bp = p & 31;
        float a0 = t[bp * 2][d], a1 = t[bp * 2 + 1][d];
        __nv_bfloat16 h0 = __float2bfloat16_rn(a0);
        __nv_bfloat16 h1 = __float2bfloat16_rn(a1);
        __nv_bfloat16 l0 = __float2bfloat16_rn(a0 - __bfloat162float(h0));
        __nv_bfloat16 l1 = __float2bfloat16_rn(a1 - __bfloat162float(h1));
        size_t idx = (size_t)(dt * 64 + d) * BSZ + bt * 64 + bp * 2;
        *(uint32_t*)((char*)g_xthi + idx * 2) = pk2(h0, h1);
        *(uint32_t*)((char*)g_xtlo + idx * 2) = pk2(l0, l1);
    }
}

// ============================================================
// Kernel 2: distance GEMM (split-fp16 HMMA, ldmatrix) + argmin.
// 512 thr = 16 warps: wb=wid>>2 (32 b), wj=wid&3 (32 j).
// W streamed 128 j x 64 k hi/lo, cp.async double-buffered.
// ============================================================
#define XS_STRIDE 528                        // 512 data + 16 pad (33==1 mod 8)
#define OFF_XLO2  (128 * XS_STRIDE)          // 67584
#define OFF_WBUF  (2 * 128 * XS_STRIDE)      // 135168
#define WROW      144                        // 128 data + 16 pad
#define WLO_OFF2  (128 * WROW)               // 18432
#define WBUF_SZ   (2 * 128 * WROW)           // 36864
#define DIST_SMEM (OFF_WBUF + 2 * WBUF_SZ)   // 208896

__device__ __forceinline__ void dist_prefetch(uint32_t sbase, int ci,
                                              int jbase, int tid) {
    int jt = ci >> 2, kc = ci & 3;
    uint32_t dbuf = sbase + OFF_WBUF + (uint32_t)(ci & 1) * WBUF_SZ;
    size_t gro = ((size_t)(jbase + jt * 128)) * KDIM + kc * 64;
#pragma unroll
    for (int t = 0; t < 2; t++) {
        int i = tid + 512 * t;               // 1024 segs per array
        int r = i >> 3, s = i & 7;
        const char* sh = (const char*)(g_whi + gro + (size_t)r * KDIM) + s * 16;
        const char* sl = (const char*)(g_wlo + gro + (size_t)r * KDIM) + s * 16;
        cpa16(dbuf + r * WROW + s * 16, sh);
        cpa16(dbuf + WLO_OFF2 + r * WROW + s * 16, sl);
    }
}

__global__ void __launch_bounds__(512, 1)
ker_dist_mma() {
    char* base = (char*)sm;
    uint32_t sbase = smem_u32(base);
    const int tid  = threadIdx.x;
    const int lane = tid & 31;
    const int wid  = tid >> 5;
    const int wb   = wid >> 2;        // 0..3 -> 32 b
    const int wj   = wid & 3;         // 0..3 -> 32 j
    const int g    = lane >> 2;
    const int c2   = (lane & 3) * 2;
    const int b0   = blockIdx.x * 128;
    const int half = blockIdx.y;
    const int jbase = half * 8192;

    // ldmatrix lane-address components
    const int la15   = lane & 15;                       // A row select
    const int laKA   = (lane >> 4) << 4;                // A k-byte select
    const int laRB   = (lane & 7) + ((lane >> 4) << 3); // B row select
    const int laKB   = ((lane >> 3) & 1) << 4;          // B k-byte select

    // ---- load X tile (hi/lo fp16), 128 rows x 512B ----
#pragma unroll
    for (int t = 0; t < 8; t++) {
        int i = tid + 512 * t;               // 4096 segs per array
        int r = i >> 5, s = i & 31;
        *(uint4*)(base + r * XS_STRIDE + s * 16) =
            *(const uint4*)((const char*)(g_xhi + (size_t)(b0 + r) * KDIM) + s * 16);
        *(uint4*)(base + OFF_XLO2 + r * XS_STRIDE + s * 16) =
            *(const uint4*)((const char*)(g_xlo + (size_t)(b0 + r) * KDIM) + s * 16);
    }

    float bz[4];
    int   bj[4];
#pragma unroll
    for (int i = 0; i < 4; i++) { bz[i] = FLT_MAX; bj[i] = 0; }

    dist_prefetch(sbase, 0, jbase, tid);
    CPA_COMMIT();

    float acc[2][4][4];

    for (int ci = 0; ci < 256; ci++) {
        const int jt = ci >> 2, kc = ci & 3;
        if (ci + 1 < 256) dist_prefetch(sbase, ci + 1, jbase, tid);
        CPA_COMMIT();
        CPA_WAIT1();
        __syncthreads();

        if (kc == 0) {
#pragma unroll
            for (int bt = 0; bt < 2; bt++)
#pragma unroll
                for (int nt = 0; nt < 4; nt++)
#pragma unroll
                    for (int r = 0; r < 4; r++) acc[bt][nt][r] = 0.f;
        }

        const uint32_t wboff = sbase + OFF_WBUF + (uint32_t)(ci & 1) * WBUF_SZ;
#pragma unroll
        for (int ks = 0; ks < 4; ks++) {
            // A fragments via ldmatrix.x4 (hi & lo), 2 b-tiles
            uint32_t ah[2][4], al[2][4];
            const int kbX = (kc * 64 + ks * 16) * 2 + laKA;
#pragma unroll
            for (int bt = 0; bt < 2; bt++) {
                uint32_t ra = sbase + (wb * 32 + bt * 16 + la15) * XS_STRIDE + kbX;
                ldsm_x4(ah[bt][0], ah[bt][1], ah[bt][2], ah[bt][3], ra);
                ldsm_x4(al[bt][0], al[bt][1], al[bt][2], al[bt][3], ra + OFF_XLO2);
            }
            const int kbW = ks * 32 + laKB;
#pragma unroll
            for (int ntp = 0; ntp < 2; ntp++) {
                uint32_t rb = wboff + (wj * 32 + ntp * 16 + laRB) * WROW + kbW;
                uint32_t bh0, bh1, bh2, bh3, bl0, bl1, bl2, bl3;
                ldsm_x4(bh0, bh1, bh2, bh3, rb);
                ldsm_x4(bl0, bl1, bl2, bl3, rb + WLO_OFF2);
#pragma unroll
                for (int bt = 0; bt < 2; bt++) {
                    float* A0 = acc[bt][ntp * 2];
                    float* A1 = acc[bt][ntp * 2 + 1];
                    mma_f16(A0, ah[bt][0], ah[bt][1], ah[bt][2], ah[bt][3], bh0, bh1);
                    mma_f16(A0, ah[bt][0], ah[bt][1], ah[bt][2], ah[bt][3], bl0, bl1);
                    mma_f16(A0, al[bt][0], al[bt][1], al[bt][2], al[bt][3], bh0, bh1);
                    mma_f16(A1, ah[bt][0], ah[bt][1], ah[bt][2], ah[bt][3], bh2, bh3);
                    mma_f16(A1, ah[bt][0], ah[bt][1], ah[bt][2], ah[bt][3], bl2, bl3);
                    mma_f16(A1, al[bt][0], al[bt][1], al[bt][2], al[bt][3], bh2, bh3);
                }
            }
        }

        if (kc == 3) {
            const int j0 = jt * 128 + wj * 32;
#pragma unroll
            for (int nt = 0; nt < 4; nt++) {
                int jg = j0 + nt * 8 + c2;
                float w0 = g_wsq[jbase + jg];
                float w1 = g_wsq[jbase + jg + 1];
#pragma unroll
                for (int bt = 0; bt < 2; bt++) {
                    float z00 = fmaf(-2.f, acc[bt][nt][0], w0);
                    float z01 = fmaf(-2.f, acc[bt][nt][1], w1);
                    float z10 = fmaf(-2.f, acc[bt][nt][2], w0);
                    float z11 = fmaf(-2.f, acc[bt][nt][3], w1);
                    int s0 = bt * 2, s1 = bt * 2 + 1;
                    if (z00 < bz[s0]) { bz[s0] = z00; bj[s0] = jg; }
                    if (z01 < bz[s0]) { bz[s0] = z01; bj[s0] = jg + 1; }
                    if (z10 < bz[s1]) { bz[s1] = z10; bj[s1] = jg; }
                    if (z11 < bz[s1]) { bz[s1] = z11; bj[s1] = jg + 1; }
                }
            }
        }
        __syncthreads();
    }

    // ---- cross-lane argmin reduction (c bits) ----
#pragma unroll
    for (int i = 0; i < 4; i++) {
        float z = bz[i]; int j = bj[i];
#pragma unroll
        for (int off = 1; off <= 2; off <<= 1) {
            float oz = __shfl_xor_sync(0xffffffffu, z, off);
            int   oj = __shfl_xor_sync(0xffffffffu, j, off);
            if (oz < z || (oz == z && oj < j)) { z = oz; j = oj; }
        }
        bz[i] = z; bj[i] = j;
    }

    // ---- cross-warp reduction via smem ----
    float* sz = (float*)(base + OFF_WBUF);
    int*   sj = (int*)(base + OFF_WBUF + 2048);
    if ((lane & 3) == 0) {
#pragma unroll
        for (int i = 0; i < 4; i++) {
            int bt = i >> 1, h = i & 1;
            int row = wb * 32 + bt * 16 + g + 8 * h;
            sz[row * 4 + wj] = bz[i];
            sj[row * 4 + wj] = bj[i];
        }
    }
    __syncthreads();
    if (tid < 128) {
        float z = sz[tid * 4]; int j = sj[tid * 4];
#pragma unroll
        for (int t = 1; t < 4; t++) {
            float oz = sz[tid * 4 + t]; int oj = sj[tid * 4 + t];
            if (oz < z || (oz == z && oj < j)) { z = oz; j = oj; }
        }
        g_pz[half * BSZ + b0 + tid] = z;
        g_pj[half * BSZ + b0 + tid] = jbase + j;
    }
}

// ============================================================
// Kernel 3: combine halves -> BMU -> neighborhood factors
// ============================================================
__global__ void ker_pxpy() {
    int i = blockIdx.x;
    float d  = g_sched[0];
    float lr = g_sched[1];
    float fi = (float)i;
    for (int b = threadIdx.x; b < BSZ; b += 256) {
        float z0 = g_pz[b], z1 = g_pz[BSZ + b];
        int bmu = (z1 < z0) ? g_pj[BSZ + b] : g_pj[b];
        float dr = fi - (float)(bmu >> 7);
        float dc = fi - (float)(bmu & 127);
        g_pxT[(size_t)i * BSZ + b] = expf(-(dr * dr) / d);
        g_pyT[(size_t)i * BSZ + b] = lr * expf(-(dc * dc) / d);
    }
}

// ============================================================
// Kernel 4: numer (split-bf16 HMMA, ldmatrix) + fused denom.
// One CTA per m, 512 thr = 16 warps: wn=wid>>2 (32 n), wd=wid&3 (64 d).
// K=8192 over b in 128 chunks of 64 (single-buffered, R5 structure).
// ============================================================
#define N_ROW    144
#define N_ALO    (128 * N_ROW)               // 18432
#define N_XLO    (256 * N_ROW)               // 36864
#define OFF_DSUM 0
#define OFF_A0   512
#define OFF_X0   (OFF_A0 + 2 * N_ALO)        // 37376
#define NUMER_SMEM (OFF_X0 + 2 * N_XLO)      // 111104

__global__ void __launch_bounds__(512, 1)
ker_numer_tc(const float* __restrict__ Wold, float* __restrict__ OUT) {
    char* base = (char*)sm;
    uint32_t sbase = smem_u32(base);
    float* dsum = (float*)(base + OFF_DSUM);

    const int tid  = threadIdx.x;
    const int wid  = tid >> 5;
    const int lane = tid & 31;
    const int m    = blockIdx.x;

    const int n0 = (wid >> 2) * 32;
    const int d0 = (wid & 3) * 64;
    const int g  = lane >> 2;
    const int c2 = (lane & 3) * 2;

    const int la15 = lane & 15;
    const int laKA = (lane >> 4) << 4;
    const int laRB = (lane & 7) + ((lane >> 4) << 3);
    const int laKB = ((lane >> 3) & 1) << 4;

    if (tid < 128) dsum[tid] = 0.f;

    float acc[2][8][4];
#pragma unroll
    for (int mt = 0; mt < 2; mt++)
#pragma unroll
        for (int nt = 0; nt < 8; nt++)
#pragma unroll
            for (int r = 0; r < 4; r++) acc[mt][nt][r] = 0.f;

    const float* pxm = g_pxT + (size_t)m * BSZ;
    const int bg = tid & 7;            // 8 b per thread
    const int nrow = tid >> 3;         // 0..63, +64 for s=1
    float dden[2] = {0.f, 0.f};

    for (int ch = 0; ch < 128; ch++) {
        const int b0c = ch * 64;
        __syncthreads();

        // ---- stage X^T (hi/lo): 256 d-rows x 64 b ----
#pragma unroll
        for (int t = 0; t < 4; t++) {
            int i = tid + 512 * t;          // 2048 segs per array
            int r = i >> 3, s = i & 7;
            size_t go = ((size_t)r * BSZ + b0c + s * 8) * 2;
            *(uint4*)(base + OFF_X0 + r * N_ROW + s * 16) =
                *(const uint4*)((const char*)g_xthi + go);
            *(uint4*)(base + OFF_X0 + N_XLO + r * N_ROW + s * 16) =
                *(const uint4*)((const char*)g_xtlo + go);
        }

        // ---- stage A (hi/lo): 128 n-rows x 64 b + denom ----
        float4 px0 = *(const float4*)(pxm + b0c + bg * 8);
        float4 px1 = *(const float4*)(pxm + b0c + bg * 8 + 4);
        float pxv[8] = {px0.x, px0.y, px0.z, px0.w, px1.x, px1.y, px1.z, px1.w};
#pragma unroll
        for (int s = 0; s < 2; s++) {
            int n = nrow + 64 * s;
            const float* py = g_pyT + (size_t)n * BSZ + b0c + bg * 8;
            float4 p0 = *(const float4*)py;
            float4 p1 = *(const float4*)(py + 4);
            float a[8] = {pxv[0]*p0.x, pxv[1]*p0.y, pxv[2]*p0.z, pxv[3]*p0.w,
                          pxv[4]*p1.x, pxv[5]*p1.y, pxv[6]*p1.z, pxv[7]*p1.w};
            float ssum = 0.f;
            __nv_bfloat16 h[8], l[8];
#pragma unroll
            for (int j = 0; j < 8; j++) {
                ssum += a[j];
                h[j] = __float2bfloat16_rn(a[j]);
                l[j] = __float2bfloat16_rn(a[j] - __bfloat162float(h[j]));
            }
            dden[s] += ssum;
            uint4 hv = make_uint4(pk2(h[0],h[1]), pk2(h[2],h[3]),
                                  pk2(h[4],h[5]), pk2(h[6],h[7]));
            uint4 lv = make_uint4(pk2(l[0],l[1]), pk2(l[2],l[3]),
                                  pk2(l[4],l[5]), pk2(l[6],l[7]));
            uint32_t so = n * N_ROW + bg * 16;
            *(uint4*)(base + OFF_A0 + so) = hv;
            *(uint4*)(base + OFF_A0 + N_ALO + so) = lv;
        }
        __syncthreads();

        // ---- MMAs ----
#pragma unroll
        for (int ks = 0; ks < 4; ks++) {
            uint32_t ah[2][4], al[2][4];
            const int kbA = ks * 32 + laKA;
#pragma unroll
            for (int bt = 0; bt < 2; bt++) {
                uint32_t ra = sbase + OFF_A0 + (n0 + bt * 16 + la15) * N_ROW + kbA;
                ldsm_x4(ah[bt][0], ah[bt][1], ah[bt][2], ah[bt][3], ra);
                ldsm_x4(al[bt][0], al[bt][1], al[bt][2], al[bt][3], ra + N_ALO);
            }
            const int kbB = ks * 32 + laKB;
#pragma unroll
            for (int ntp = 0; ntp < 4; ntp++) {
                uint32_t rb = sbase + OFF_X0 + (d0 + ntp * 16 + laRB) * N_ROW + kbB;
                uint32_t bh0, bh1, bh2, bh3, bl0, bl1, bl2, bl3;
                ldsm_x4(bh0, bh1, bh2, bh3, rb);
                ldsm_x4(bl0, bl1, bl2, bl3, rb + N_XLO);
#pragma unroll
                for (int bt = 0; bt < 2; bt++) {
                    float* A0 = acc[bt][ntp * 2];
                    float* A1 = acc[bt][ntp * 2 + 1];
                    mma_bf16(A0, ah[bt][0], ah[bt][1], ah[bt][2], ah[bt][3], bh0, bh1);
                    mma_bf16(A0, ah[bt][0], ah[bt][1], ah[bt][2], ah[bt][3], bl0, bl1);
                    mma_bf16(A0, al[bt][0], al[bt][1], al[bt][2], al[bt][3], bh0, bh1);
                    mma_bf16(A1, ah[bt][0], ah[bt][1], ah[bt][2], ah[bt][3], bh2, bh3);
                    mma_bf16(A1, ah[bt][0], ah[bt][1], ah[bt][2], ah[bt][3], bl2, bl3);
                    mma_bf16(A1, al[bt][0], al[bt][1], al[bt][2], al[bt][3], bh2, bh3);
                }
            }
        }
    }

    // ---- denom reduction ----
    __syncthreads();
#pragma unroll
    for (int s = 0; s < 2; s++)
        atomicAdd(&dsum[nrow + 64 * s], dden[s]);
    __syncthreads();

    // ---- epilogue ----
#pragma unroll
    for (int mt = 0; mt < 2; mt++) {
#pragma unroll
        for (int gg = 0; gg < 2; gg++) {
            int n = n0 + mt * 16 + g + gg * 8;
            float den = dsum[n];
            size_t rb = ((size_t)(m * 128 + n)) * KDIM;
#pragma unroll
            for (int nt = 0; nt < 8; nt++) {
                int dcol = d0 + nt * 8 + c2;
                float v0 = acc[mt][nt][gg * 2];
                float v1 = acc[mt][nt][gg * 2 + 1];
                float2 o;
                if (den != 0.f) {
                    o.x = v0 / den; o.y = v1 / den;
                } else {
                    o.x = Wold[rb + dcol]; o.y = Wold[rb + dcol + 1];
                }
                *(float2*)(OUT + rb + dcol) = o;
            }
        }
    }
}

// ============================================================
extern "C" void kernel_launch(void* const* d_in, const int* in_sizes, int n_in,
                              void* d_out, int out_size) {
    (void)in_sizes; (void)n_in; (void)out_size;
    const float* data    = (const float*)d_in[0];
    const float* weights = (const float*)d_in[1];
    const int*   itp     = (const int*)d_in[2];
    float*       out     = (float*)d_out;

    cudaFuncSetAttribute(ker_dist_mma, cudaFuncAttributeMaxDynamicSharedMemorySize,
                         DIST_SMEM);
    cudaFuncSetAttribute(ker_numer_tc, cudaFuncAttributeMaxDynamicSharedMemorySize,
                         NUMER_SMEM);

    ker_sq<<<MN / 8, 256>>>(weights, itp);
    ker_split<<<(WPAIRS + XPAIRS) / 256, 256>>>(weights, data);
    ker_prep<<<dim3(BSZ / 64, KDIM / 64), 256>>>(data);
    ker_dist_mma<<<dim3(64, 2), 512, DIST_SMEM>>>();
    ker_pxpy<<<128, 256>>>();
    ker_numer_tc<<<128, 512, NUMER_SMEM>>>(weights, out);
}

// round 8
// speedup vs baseline: 1.2113x; 1.0569x over previous
#include <cuda_runtime.h>
#include <cuda_bf16.h>
#include <cuda_fp16.h>
#include <math.h>
#include <stdint.h>
#include <float.h>

#define BSZ   8192
#define MDIM  128
#define NDIM  128
#define KDIM  256
#define MN    16384

// -------- device scratch --------
__device__ float g_wsq[MN];
__device__ float g_pxT[MDIM * BSZ];    // [m][b]
__device__ float g_pyT[NDIM * BSZ];    // [n][b]
__device__ float g_sched[2];           // [0] = 2*sigma^2, [1] = lr
__device__ __nv_bfloat16 g_xthi[KDIM * BSZ];  // X^T hi (bf16) [d][b]
__device__ __nv_bfloat16 g_xtlo[KDIM * BSZ];  // X^T lo (bf16) [d][b]
__device__ __align__(16) __half g_whi[MN * KDIM];   // W hi (fp16) [j][k]
__device__ __align__(16) __half g_wlo[MN * KDIM];   // W lo
__device__ __align__(16) __half g_xhi[BSZ * KDIM];  // X hi (fp16) [b][k]
__device__ __align__(16) __half g_xlo[BSZ * KDIM];  // X lo
__device__ float g_pz[2 * BSZ];
__device__ int   g_pj[2 * BSZ];

extern __shared__ float sm[];

__device__ __forceinline__ uint32_t smem_u32(const void* p) {
    uint32_t a;
    asm("{ .reg .u64 t; cvta.to.shared.u64 t, %1; cvt.u32.u64 %0, t; }"
        : "=r"(a) : "l"(p));
    return a;
}
__device__ __forceinline__ uint32_t pk2(__nv_bfloat16 a, __nv_bfloat16 b) {
    __nv_bfloat162 t = __halves2bfloat162(a, b);
    return *reinterpret_cast<uint32_t*>(&t);
}
__device__ __forceinline__ void mma_bf16(float* d,
                                         uint32_t a0, uint32_t a1,
                                         uint32_t a2, uint32_t a3,
                                         uint32_t b0, uint32_t b1) {
    asm volatile(
        "mma.sync.aligned.m16n8k16.row.col.f32.bf16.bf16.f32 "
        "{%0,%1,%2,%3}, {%4,%5,%6,%7}, {%8,%9}, {%0,%1,%2,%3};"
        : "+f"(d[0]), "+f"(d[1]), "+f"(d[2]), "+f"(d[3])
        : "r"(a0), "r"(a1), "r"(a2), "r"(a3), "r"(b0), "r"(b1));
}
__device__ __forceinline__ void mma_f16(float* d,
                                        uint32_t a0, uint32_t a1,
                                        uint32_t a2, uint32_t a3,
                                        uint32_t b0, uint32_t b1) {
    asm volatile(
        "mma.sync.aligned.m16n8k16.row.col.f32.f16.f16.f32 "
        "{%0,%1,%2,%3}, {%4,%5,%6,%7}, {%8,%9}, {%0,%1,%2,%3};"
        : "+f"(d[0]), "+f"(d[1]), "+f"(d[2]), "+f"(d[3])
        : "r"(a0), "r"(a1), "r"(a2), "r"(a3), "r"(b0), "r"(b1));
}
__device__ __forceinline__ void ldsm_x4(uint32_t& r0, uint32_t& r1,
                                        uint32_t& r2, uint32_t& r3,
                                        uint32_t addr) {
    asm volatile("ldmatrix.sync.aligned.m8n8.x4.shared.b16 {%0,%1,%2,%3}, [%4];"
                 : "=r"(r0), "=r"(r1), "=r"(r2), "=r"(r3) : "r"(addr));
}
__device__ __forceinline__ void cpa16(uint32_t saddr, const void* g) {
    asm volatile("cp.async.cg.shared.global [%0], [%1], 16;"
                 :: "r"(saddr), "l"(g));
}
#define CPA_COMMIT() asm volatile("cp.async.commit_group;" ::: "memory")
#define CPA_WAIT0()  asm volatile("cp.async.wait_group 0;" ::: "memory")

// ============================================================
// Kernel 1: wsq + schedule
// ============================================================
__global__ void ker_sq(const float* __restrict__ W,
                       const int*  __restrict__ itp) {
    if (blockIdx.x == 0 && threadIdx.x == 0) {
        int it = itp[0];
        double TAU   = 20.0 / log(64.0);
        double sigma = 64.0 * exp(-(double)it / TAU);
        g_sched[0] = (float)(2.0 * sigma * sigma);
        g_sched[1] = (float)(0.5 * exp(-(double)it / 20.0));
    }
    int warp = (blockIdx.x * blockDim.x + threadIdx.x) >> 5;
    int lane = threadIdx.x & 31;
    if (warp >= MN) return;
    const float* src = W + (size_t)warp * KDIM;
    float s = 0.f;
#pragma unroll
    for (int c = lane; c < KDIM; c += 32) { float v = src[c]; s += v * v; }
#pragma unroll
    for (int o = 16; o > 0; o >>= 1) s += __shfl_down_sync(0xffffffffu, s, o);
    if (lane == 0) g_wsq[warp] = s;
}

// ============================================================
// Kernel 1b: fp16 hi/lo splits of W and X (dist inputs)
// ============================================================
#define WPAIRS (MN * KDIM / 2)
#define XPAIRS (BSZ * KDIM / 2)
__global__ void ker_split(const float* __restrict__ W,
                          const float* __restrict__ X) {
    int idx = blockIdx.x * 256 + threadIdx.x;
    const float* src;
    __half *dhi, *dlo;
    int p;
    if (idx < WPAIRS) {
        src = W; dhi = g_whi; dlo = g_wlo; p = idx;
    } else if (idx < WPAIRS + XPAIRS) {
        src = X; dhi = g_xhi; dlo = g_xlo; p = idx - WPAIRS;
    } else return;
    float2 v = *(const float2*)(src + (size_t)p * 2);
    __half h0 = __float2half_rn(v.x);
    __half h1 = __float2half_rn(v.y);
    __half l0 = __float2half_rn(v.x - __half2float(h0));
    __half l1 = __float2half_rn(v.y - __half2float(h1));
    *(__half2*)(dhi + (size_t)p * 2) = __halves2half2(h0, h1);
    *(__half2*)(dlo + (size_t)p * 2) = __halves2half2(l0, l1);
}

// ============================================================
// Kernel 1c: X -> transposed split-bf16 (numer inputs)
// ============================================================
__global__ void ker_prep(const float* __restrict__ X) {
    __shared__ float t[64][65];
    int bt = blockIdx.x;
    int dt = blockIdx.y;
    int tid = threadIdx.x;
#pragma unroll
    for (int s = 0; s < 16; s++) {
        int e = tid + 256 * s;
        int b = e >> 6, d = e & 63;
        t[b][d] = X[(size_t)(bt * 64 + b) * KDIM + dt * 64 + d];
    }
    __syncthreads();
#pragma unroll
    for (int s = 0; s < 8; s++) {
        int p = tid + 256 * s;
        int d = p >> 5, bp = p & 31;
        float a0 = t[bp * 2][d], a1 = t[bp * 2 + 1][d];
        __nv_bfloat16 h0 = __float2bfloat16_rn(a0);
        __nv_bfloat16 h1 = __float2bfloat16_rn(a1);
        __nv_bfloat16 l0 = __float2bfloat16_rn(a0 - __bfloat162float(h0));
        __nv_bfloat16 l1 = __float2bfloat16_rn(a1 - __bfloat162float(h1));
        size_t idx = (size_t)(dt * 64 + d) * BSZ + bt * 64 + bp * 2;
        *(uint32_t*)((char*)g_xthi + idx * 2) = pk2(h0, h1);
        *(uint32_t*)((char*)g_xtlo + idx * 2) = pk2(l0, l1);
    }
}

// ============================================================
// Kernel 2: distance GEMM (split-fp16 HMMA, ldmatrix) + argmin.
// 512 thr = 16 warps: wb (32 b), wj (32 j). W streamed 128j x 64k
// hi/lo, cp.async double-buffered, ONE sync per iteration.
// MMAs term-major (acc reuse distance 8).
// ============================================================
#define XS_STRIDE 528                        // 512 data + 16 pad
#define OFF_XLO2  (128 * XS_STRIDE)          // 67584
#define OFF_WBUF  (2 * 128 * XS_STRIDE)      // 135168
#define WROW      144                        // 128 data + 16 pad
#define WLO_OFF2  (128 * WROW)               // 18432
#define WBUF_SZ   (2 * 128 * WROW)           // 36864
#define DIST_SMEM (OFF_WBUF + 2 * WBUF_SZ)   // 208896

__device__ __forceinline__ void dist_prefetch(uint32_t sbase, int ci,
                                              int jbase, int tid) {
    int jt = ci >> 2, kc = ci & 3;
    uint32_t dbuf = sbase + OFF_WBUF + (uint32_t)(ci & 1) * WBUF_SZ;
    size_t gro = ((size_t)(jbase + jt * 128)) * KDIM + kc * 64;
#pragma unroll
    for (int t = 0; t < 2; t++) {
        int i = tid + 512 * t;               // 1024 segs per array
        int r = i >> 3, s = i & 7;
        const char* sh = (const char*)(g_whi + gro + (size_t)r * KDIM) + s * 16;
        const char* sl = (const char*)(g_wlo + gro + (size_t)r * KDIM) + s * 16;
        cpa16(dbuf + r * WROW + s * 16, sh);
        cpa16(dbuf + WLO_OFF2 + r * WROW + s * 16, sl);
    }
}

__global__ void __launch_bounds__(512, 1)
ker_dist_mma() {
    char* base = (char*)sm;
    uint32_t sbase = smem_u32(base);
    const int tid  = threadIdx.x;
    const int lane = tid & 31;
    const int wid  = tid >> 5;
    const int wb   = wid >> 2;        // 0..3 -> 32 b
    const int wj   = wid & 3;         // 0..3 -> 32 j
    const int g    = lane >> 2;
    const int c2   = (lane & 3) * 2;
    const int b0   = blockIdx.x * 128;
    const int half = blockIdx.y;
    const int jbase = half * 8192;

    const int la15 = lane & 15;
    const int laKA = (lane >> 4) << 4;
    const int laRB = (lane & 7) + ((lane >> 4) << 3);
    const int laKB = ((lane >> 3) & 1) << 4;

    // ---- load X tile (hi/lo fp16), 128 rows x 512B ----
#pragma unroll
    for (int t = 0; t < 8; t++) {
        int i = tid + 512 * t;
        int r = i >> 5, s = i & 31;
        *(uint4*)(base + r * XS_STRIDE + s * 16) =
            *(const uint4*)((const char*)(g_xhi + (size_t)(b0 + r) * KDIM) + s * 16);
        *(uint4*)(base + OFF_XLO2 + r * XS_STRIDE + s * 16) =
            *(const uint4*)((const char*)(g_xlo + (size_t)(b0 + r) * KDIM) + s * 16);
    }

    float bz[4];
    int   bj[4];
#pragma unroll
    for (int i = 0; i < 4; i++) { bz[i] = FLT_MAX; bj[i] = 0; }

    dist_prefetch(sbase, 0, jbase, tid);
    CPA_COMMIT();

    float acc[2][4][4];

    for (int ci = 0; ci < 256; ci++) {
        const int jt = ci >> 2, kc = ci & 3;

        CPA_WAIT0();
        __syncthreads();     // buffer ci ready everywhere; everyone done with ci-1
        if (ci + 1 < 256) {
            dist_prefetch(sbase, ci + 1, jbase, tid);
            CPA_COMMIT();
        }

        if (kc == 0) {
#pragma unroll
            for (int bt = 0; bt < 2; bt++)
#pragma unroll
                for (int nt = 0; nt < 4; nt++)
#pragma unroll
                    for (int r = 0; r < 4; r++) acc[bt][nt][r] = 0.f;
        }

        const uint32_t wboff = sbase + OFF_WBUF + (uint32_t)(ci & 1) * WBUF_SZ;
#pragma unroll
        for (int ks = 0; ks < 4; ks++) {
            uint32_t ah[2][4], al[2][4];
            const int kbX = (kc * 64 + ks * 16) * 2 + laKA;
#pragma unroll
            for (int bt = 0; bt < 2; bt++) {
                uint32_t ra = sbase + (wb * 32 + bt * 16 + la15) * XS_STRIDE + kbX;
                ldsm_x4(ah[bt][0], ah[bt][1], ah[bt][2], ah[bt][3], ra);
                ldsm_x4(al[bt][0], al[bt][1], al[bt][2], al[bt][3], ra + OFF_XLO2);
            }
            uint32_t bh[2][4], bl[2][4];
            const int kbW = ks * 32 + laKB;
#pragma unroll
            for (int ntp = 0; ntp < 2; ntp++) {
                uint32_t rb = wboff + (wj * 32 + ntp * 16 + laRB) * WROW + kbW;
                ldsm_x4(bh[ntp][0], bh[ntp][1], bh[ntp][2], bh[ntp][3], rb);
                ldsm_x4(bl[ntp][0], bl[ntp][1], bl[ntp][2], bl[ntp][3], rb + WLO_OFF2);
            }
            // term-major: acc reuse distance = 8 MMAs
#pragma unroll
            for (int ntp = 0; ntp < 2; ntp++)
#pragma unroll
                for (int bt = 0; bt < 2; bt++) {
                    mma_f16(acc[bt][ntp*2],   ah[bt][0], ah[bt][1], ah[bt][2], ah[bt][3], bh[ntp][0], bh[ntp][1]);
                    mma_f16(acc[bt][ntp*2+1], ah[bt][0], ah[bt][1], ah[bt][2], ah[bt][3], bh[ntp][2], bh[ntp][3]);
                }
#pragma unroll
            for (int ntp = 0; ntp < 2; ntp++)
#pragma unroll
                for (int bt = 0; bt < 2; bt++) {
                    mma_f16(acc[bt][ntp*2],   ah[bt][0], ah[bt][1], ah[bt][2], ah[bt][3], bl[ntp][0], bl[ntp][1]);
                    mma_f16(acc[bt][ntp*2+1], ah[bt][0], ah[bt][1], ah[bt][2], ah[bt][3], bl[ntp][2], bl[ntp][3]);
                }
#pragma unroll
            for (int ntp = 0; ntp < 2; ntp++)
#pragma unroll
                for (int bt = 0; bt < 2; bt++) {
                    mma_f16(acc[bt][ntp*2],   al[bt][0], al[bt][1], al[bt][2], al[bt][3], bh[ntp][0], bh[ntp][1]);
                    mma_f16(acc[bt][ntp*2+1], al[bt][0], al[bt][1], al[bt][2], al[bt][3], bh[ntp][2], bh[ntp][3]);
                }
        }

        if (kc == 3) {
            const int j0 = jt * 128 + wj * 32;
#pragma unroll
            for (int nt = 0; nt < 4; nt++) {
                int jg = j0 + nt * 8 + c2;
                float w0 = g_wsq[jbase + jg];
                float w1 = g_wsq[jbase + jg + 1];
#pragma unroll
                for (int bt = 0; bt < 2; bt++) {
                    float z00 = fmaf(-2.f, acc[bt][nt][0], w0);
                    float z01 = fmaf(-2.f, acc[bt][nt][1], w1);
                    float z10 = fmaf(-2.f, acc[bt][nt][2], w0);
                    float z11 = fmaf(-2.f, acc[bt][nt][3], w1);
                    int s0 = bt * 2, s1 = bt * 2 + 1;
                    if (z00 < bz[s0]) { bz[s0] = z00; bj[s0] = jg; }
                    if (z01 < bz[s0]) { bz[s0] = z01; bj[s0] = jg + 1; }
                    if (z10 < bz[s1]) { bz[s1] = z10; bj[s1] = jg; }
                    if (z11 < bz[s1]) { bz[s1] = z11; bj[s1] = jg + 1; }
                }
            }
        }
    }

    // ---- cross-lane argmin reduction (c bits) ----
#pragma unroll
    for (int i = 0; i < 4; i++) {
        float z = bz[i]; int j = bj[i];
#pragma unroll
        for (int off = 1; off <= 2; off <<= 1) {
            float oz = __shfl_xor_sync(0xffffffffu, z, off);
            int   oj = __shfl_xor_sync(0xffffffffu, j, off);
            if (oz < z || (oz == z && oj < j)) { z = oz; j = oj; }
        }
        bz[i] = z; bj[i] = j;
    }

    // ---- cross-warp reduction via smem ----
    __syncthreads();
    float* sz = (float*)(base + OFF_WBUF);
    int*   sj = (int*)(base + OFF_WBUF + 2048);
    if ((lane & 3) == 0) {
#pragma unroll
        for (int i = 0; i < 4; i++) {
            int bt = i >> 1, h = i & 1;
            int row = wb * 32 + bt * 16 + g + 8 * h;
            sz[row * 4 + wj] = bz[i];
            sj[row * 4 + wj] = bj[i];
        }
    }
    __syncthreads();
    if (tid < 128) {
        float z = sz[tid * 4]; int j = sj[tid * 4];
#pragma unroll
        for (int t = 1; t < 4; t++) {
            float oz = sz[tid * 4 + t]; int oj = sj[tid * 4 + t];
            if (oz < z || (oz == z && oj < j)) { z = oz; j = oj; }
        }
        g_pz[half * BSZ + b0 + tid] = z;
        g_pj[half * BSZ + b0 + tid] = jbase + j;
    }
}

// ============================================================
// Kernel 3: combine halves -> BMU -> neighborhood factors
// ============================================================
__global__ void ker_pxpy() {
    int i = blockIdx.x;
    float d  = g_sched[0];
    float lr = g_sched[1];
    float fi = (float)i;
    for (int b = threadIdx.x; b < BSZ; b += 256) {
        float z0 = g_pz[b], z1 = g_pz[BSZ + b];
        int bmu = (z1 < z0) ? g_pj[BSZ + b] : g_pj[b];
        float dr = fi - (float)(bmu >> 7);
        float dc = fi - (float)(bmu & 127);
        g_pxT[(size_t)i * BSZ + b] = expf(-(dr * dr) / d);
        g_pyT[(size_t)i * BSZ + b] = lr * expf(-(dc * dc) / d);
    }
}

// ============================================================
// Kernel 4: numer (split-bf16 HMMA, ldmatrix) + fused denom.
// One CTA per m, 512 thr. K=8192 over b in 128 chunks of 64,
// double-buffered: X via cp.async, A staged one chunk ahead.
// ONE sync per iteration; term-major MMAs.
// ============================================================
#define N_ROW    144
#define N_ALO    (128 * N_ROW)               // 18432
#define N_ABUF   (2 * N_ALO)                 // 36864
#define N_XLO    (256 * N_ROW)               // 36864
#define N_XBUF   (2 * N_XLO)                 // 73728
#define OFF_DSUM 0
#define OFF_A0   512
#define OFF_X0   (OFF_A0 + 2 * N_ABUF)       // 74240
#define NUMER_SMEM (OFF_X0 + 2 * N_XBUF)     // 221696

__global__ void __launch_bounds__(512, 1)
ker_numer_tc(const float* __restrict__ Wold, float* __restrict__ OUT) {
    char* base = (char*)sm;
    uint32_t sbase = smem_u32(base);
    float* dsum = (float*)(base + OFF_DSUM);

    const int tid  = threadIdx.x;
    const int wid  = tid >> 5;
    const int lane = tid & 31;
    const int m    = blockIdx.x;

    const int n0 = (wid >> 2) * 32;
    const int d0 = (wid & 3) * 64;
    const int g  = lane >> 2;
    const int c2 = (lane & 3) * 2;

    const int la15 = lane & 15;
    const int laKA = (lane >> 4) << 4;
    const int laRB = (lane & 7) + ((lane >> 4) << 3);
    const int laKB = ((lane >> 3) & 1) << 4;

    if (tid < 128) dsum[tid] = 0.f;

    float acc[2][8][4];
#pragma unroll
    for (int mt = 0; mt < 2; mt++)
#pragma unroll
        for (int nt = 0; nt < 8; nt++)
#pragma unroll
            for (int r = 0; r < 4; r++) acc[mt][nt][r] = 0.f;

    const float* pxm = g_pxT + (size_t)m * BSZ;
    const int bg = tid & 7;            // 8 b per thread
    const int nrow = tid >> 3;         // 0..63, +64 for s=1
    float dden[2] = {0.f, 0.f};

    // ---- helpers ----
#define NUMER_XPREF(ch) do {                                                   \
        int b0c = (ch) * 64;                                                   \
        uint32_t xb = sbase + OFF_X0 + (uint32_t)((ch) & 1) * N_XBUF;          \
        _Pragma("unroll")                                                      \
        for (int t = 0; t < 4; t++) {                                          \
            int i = tid + 512 * t;                                             \
            int r = i >> 3, s = i & 7;                                         \
            size_t go = ((size_t)r * BSZ + b0c + s * 8) * 2;                   \
            cpa16(xb + r * N_ROW + s * 16, (const char*)g_xthi + go);          \
            cpa16(xb + N_XLO + r * N_ROW + s * 16, (const char*)g_xtlo + go);  \
        }                                                                      \
    } while (0)

#define NUMER_ASTAGE(ch) do {                                                  \
        int b0c = (ch) * 64;                                                   \
        uint32_t ab = (uint32_t)(OFF_A0 + ((ch) & 1) * N_ABUF);                \
        float4 px0 = *(const float4*)(pxm + b0c + bg * 8);                     \
        float4 px1 = *(const float4*)(pxm + b0c + bg * 8 + 4);                 \
        float pxv[8] = {px0.x, px0.y, px0.z, px0.w,                            \
                        px1.x, px1.y, px1.z, px1.w};                           \
        _Pragma("unroll")                                                      \
        for (int s = 0; s < 2; s++) {                                          \
            int n = nrow + 64 * s;                                             \
            const float* py = g_pyT + (size_t)n * BSZ + b0c + bg * 8;          \
            float4 p0 = *(const float4*)py;                                    \
            float4 p1 = *(const float4*)(py + 4);                              \
            float a[8] = {pxv[0]*p0.x, pxv[1]*p0.y, pxv[2]*p0.z, pxv[3]*p0.w,  \
                          pxv[4]*p1.x, pxv[5]*p1.y, pxv[6]*p1.z, pxv[7]*p1.w}; \
            float ssum = 0.f;                                                  \
            __nv_bfloat16 h[8], l[8];                                          \
            _Pragma("unroll")                                                  \
            for (int j = 0; j < 8; j++) {                                      \
                ssum += a[j];                                                  \
                h[j] = __float2bfloat16_rn(a[j]);                              \
                l[j] = __float2bfloat16_rn(a[j] - __bfloat162float(h[j]));     \
            }                                                                  \
            dden[s] += ssum;                                                   \
            uint4 hv = make_uint4(pk2(h[0],h[1]), pk2(h[2],h[3]),              \
                                  pk2(h[4],h[5]), pk2(h[6],h[7]));             \
            uint4 lv = make_uint4(pk2(l[0],l[1]), pk2(l[2],l[3]),              \
                                  pk2(l[4],l[5]), pk2(l[6],l[7]));             \
            uint32_t so = n * N_ROW + bg * 16;                                 \
            *(uint4*)(base + ab + so) = hv;                                    \
            *(uint4*)(base + ab + N_ALO + so) = lv;                            \
        }                                                                      \
    } while (0)

    // prologue: stage chunk 0
    NUMER_ASTAGE(0);
    NUMER_XPREF(0);
    CPA_COMMIT();

    for (int ch = 0; ch < 128; ch++) {
        CPA_WAIT0();
        __syncthreads();   // X(ch) + A(ch) visible; all done with buffers of ch-1

        if (ch + 1 < 128) {
            NUMER_XPREF(ch + 1);
            CPA_COMMIT();
            NUMER_ASTAGE(ch + 1);
        }

        const uint32_t abase = sbase + OFF_A0 + (uint32_t)(ch & 1) * N_ABUF;
        const uint32_t xbase = sbase + OFF_X0 + (uint32_t)(ch & 1) * N_XBUF;
#pragma unroll
        for (int ks = 0; ks < 4; ks++) {
            uint32_t ah[2][4], al[2][4];
            const int kbA = ks * 32 + laKA;
#pragma unroll
            for (int bt = 0; bt < 2; bt++) {
                uint32_t ra = abase + (n0 + bt * 16 + la15) * N_ROW + kbA;
                ldsm_x4(ah[bt][0], ah[bt][1], ah[bt][2], ah[bt][3], ra);
                ldsm_x4(al[bt][0], al[bt][1], al[bt][2], al[bt][3], ra + N_ALO);
            }
            const int kbB = ks * 32 + laKB;
#pragma unroll
            for (int h2 = 0; h2 < 2; h2++) {
                uint32_t bh[2][4], bl[2][4];
#pragma unroll
                for (int p = 0; p < 2; p++) {
                    int ntp = h2 * 2 + p;
                    uint32_t rb = xbase + (d0 + ntp * 16 + laRB) * N_ROW + kbB;
                    ldsm_x4(bh[p][0], bh[p][1], bh[p][2], bh[p][3], rb);
                    ldsm_x4(bl[p][0], bl[p][1], bl[p][2], bl[p][3], rb + N_XLO);
                }
                // term-major: acc reuse distance = 8 MMAs
#pragma unroll
                for (int p = 0; p < 2; p++)
#pragma unroll
                    for (int bt = 0; bt < 2; bt++) {
                        int nt = (h2 * 2 + p) * 2;
                        mma_bf16(acc[bt][nt],   ah[bt][0], ah[bt][1], ah[bt][2], ah[bt][3], bh[p][0], bh[p][1]);
                        mma_bf16(acc[bt][nt+1], ah[bt][0], ah[bt][1], ah[bt][2], ah[bt][3], bh[p][2], bh[p][3]);
                    }
#pragma unroll
                for (int p = 0; p < 2; p++)
#pragma unroll
                    for (int bt = 0; bt < 2; bt++) {
                        int nt = (h2 * 2 + p) * 2;
                        mma_bf16(acc[bt][nt],   ah[bt][0], ah[bt][1], ah[bt][2], ah[bt][3], bl[p][0], bl[p][1]);
                        mma_bf16(acc[bt][nt+1], ah[bt][0], ah[bt][1], ah[bt][2], ah[bt][3], bl[p][2], bl[p][3]);
                    }
#pragma unroll
                for (int p = 0; p < 2; p++)
#pragma unroll
                    for (int bt = 0; bt < 2; bt++) {
                        int nt = (h2 * 2 + p) * 2;
                        mma_bf16(acc[bt][nt],   al[bt][0], al[bt][1], al[bt][2], al[bt][3], bh[p][0], bh[p][1]);
                        mma_bf16(acc[bt][nt+1], al[bt][0], al[bt][1], al[bt][2], al[bt][3], bh[p][2], bh[p][3]);
                    }
            }
        }
    }

    // ---- denom reduction ----
    __syncthreads();
#pragma unroll
    for (int s = 0; s < 2; s++)
        atomicAdd(&dsum[nrow + 64 * s], dden[s]);
    __syncthreads();

    // ---- epilogue ----
#pragma unroll
    for (int mt = 0; mt < 2; mt++) {
#pragma unroll
        for (int gg = 0; gg < 2; gg++) {
            int n = n0 + mt * 16 + g + gg * 8;
            float den = dsum[n];
            size_t rb = ((size_t)(m * 128 + n)) * KDIM;
#pragma unroll
            for (int nt = 0; nt < 8; nt++) {
                int dcol = d0 + nt * 8 + c2;
                float v0 = acc[mt][nt][gg * 2];
                float v1 = acc[mt][nt][gg * 2 + 1];
                float2 o;
                if (den != 0.f) {
                    o.x = v0 / den; o.y = v1 / den;
                } else {
                    o.x = Wold[rb + dcol]; o.y = Wold[rb + dcol + 1];
                }
                *(float2*)(OUT + rb + dcol) = o;
            }
        }
    }
}

// ============================================================
extern "C" void kernel_launch(void* const* d_in, const int* in_sizes, int n_in,
                              void* d_out, int out_size) {
    (void)in_sizes; (void)n_in; (void)out_size;
    const float* data    = (const float*)d_in[0];
    const float* weights = (const float*)d_in[1];
    const int*   itp     = (const int*)d_in[2];
    float*       out     = (float*)d_out;

    cudaFuncSetAttribute(ker_dist_mma, cudaFuncAttributeMaxDynamicSharedMemorySize,
                         DIST_SMEM);
    cudaFuncSetAttribute(ker_numer_tc, cudaFuncAttributeMaxDynamicSharedMemorySize,
                         NUMER_SMEM);

    ker_sq<<<MN / 8, 256>>>(weights, itp);
    ker_split<<<(WPAIRS + XPAIRS) / 256, 256>>>(weights, data);
    ker_prep<<<dim3(BSZ / 64, KDIM / 64), 256>>>(data);
    ker_dist_mma<<<dim3(64, 2), 512, DIST_SMEM>>>();
    ker_pxpy<<<128, 256>>>();
    ker_numer_tc<<<128, 512, NUMER_SMEM>>>(weights, out);
}

// round 9
// speedup vs baseline: 1.4909x; 1.2308x over previous
#include <cuda_runtime.h>
#include <cuda_bf16.h>
#include <cuda_fp16.h>
#include <math.h>
#include <stdint.h>
#include <float.h>

#define BSZ   8192
#define MDIM  128
#define NDIM  128
#define KDIM  256
#define MN    16384

// -------- device scratch --------
__device__ float g_wsq[MN];
__device__ float g_pxT[MDIM * BSZ];    // [m][b]
__device__ float g_pyT[NDIM * BSZ];    // [n][b]
__device__ float g_sched[2];           // [0] = 2*sigma^2, [1] = lr
__device__ __nv_bfloat16 g_xthi[KDIM * BSZ];  // X^T hi (bf16) [d][b] (numer)
__device__ __nv_bfloat16 g_xtlo[KDIM * BSZ];  // X^T lo (bf16) [d][b] (numer)
__device__ __align__(16) __half g_whi[MN * KDIM];   // W hi (fp16) [j][k]
__device__ __align__(16) __half g_xhi[BSZ * KDIM];  // X hi (fp16) [b][k]
__device__ float g_cz[2 * BSZ * 2];    // top-2 approx scores per (half, b)
__device__ int   g_cj[2 * BSZ * 2];    // top-2 candidate j (global)
__device__ int   g_bmu[BSZ];

extern __shared__ float sm[];

__device__ __forceinline__ uint32_t smem_u32(const void* p) {
    uint32_t a;
    asm("{ .reg .u64 t; cvta.to.shared.u64 t, %1; cvt.u32.u64 %0, t; }"
        : "=r"(a) : "l"(p));
    return a;
}
__device__ __forceinline__ uint32_t pk2(__nv_bfloat16 a, __nv_bfloat16 b) {
    __nv_bfloat162 t = __halves2bfloat162(a, b);
    return *reinterpret_cast<uint32_t*>(&t);
}
__device__ __forceinline__ void mma_bf16(float* d,
                                         uint32_t a0, uint32_t a1,
                                         uint32_t a2, uint32_t a3,
                                         uint32_t b0, uint32_t b1) {
    asm volatile(
        "mma.sync.aligned.m16n8k16.row.col.f32.bf16.bf16.f32 "
        "{%0,%1,%2,%3}, {%4,%5,%6,%7}, {%8,%9}, {%0,%1,%2,%3};"
        : "+f"(d[0]), "+f"(d[1]), "+f"(d[2]), "+f"(d[3])
        : "r"(a0), "r"(a1), "r"(a2), "r"(a3), "r"(b0), "r"(b1));
}
__device__ __forceinline__ void mma_f16(float* d,
                                        uint32_t a0, uint32_t a1,
                                        uint32_t a2, uint32_t a3,
                                        uint32_t b0, uint32_t b1) {
    asm volatile(
        "mma.sync.aligned.m16n8k16.row.col.f32.f16.f16.f32 "
        "{%0,%1,%2,%3}, {%4,%5,%6,%7}, {%8,%9}, {%0,%1,%2,%3};"
        : "+f"(d[0]), "+f"(d[1]), "+f"(d[2]), "+f"(d[3])
        : "r"(a0), "r"(a1), "r"(a2), "r"(a3), "r"(b0), "r"(b1));
}
__device__ __forceinline__ void ldsm_x4(uint32_t& r0, uint32_t& r1,
                                        uint32_t& r2, uint32_t& r3,
                                        uint32_t addr) {
    asm volatile("ldmatrix.sync.aligned.m8n8.x4.shared.b16 {%0,%1,%2,%3}, [%4];"
                 : "=r"(r0), "=r"(r1), "=r"(r2), "=r"(r3) : "r"(addr));
}
__device__ __forceinline__ void cpa16(uint32_t saddr, const void* g) {
    asm volatile("cp.async.cg.shared.global [%0], [%1], 16;"
                 :: "r"(saddr), "l"(g));
}
#define CPA_COMMIT() asm volatile("cp.async.commit_group;" ::: "memory")
#define CPA_WAIT0()  asm volatile("cp.async.wait_group 0;" ::: "memory")
#define CPA_WAIT2()  asm volatile("cp.async.wait_group 2;" ::: "memory")

// top-2 merge: (z1,j1,z2,j2) sorted pair merged with (oz1,oj1,oz2,oj2)
__device__ __forceinline__ void top2_merge(float& z1, int& j1, float& z2, int& j2,
                                           float oz1, int oj1, float oz2, int oj2) {
    bool b1 = (oz1 < z1) || (oz1 == z1 && oj1 < j1);
    if (b1) {
        bool b2 = (z1 < oz2) || (z1 == oz2 && j1 < oj2);
        z2 = b2 ? z1 : oz2; j2 = b2 ? j1 : oj2;
        z1 = oz1; j1 = oj1;
    } else {
        bool b2 = (oz1 < z2) || (oz1 == z2 && oj1 < j2);
        z2 = b2 ? oz1 : z2; j2 = b2 ? oj1 : j2;
    }
}

// ============================================================
// Kernel 1: wsq + schedule
// ============================================================
__global__ void ker_sq(const float* __restrict__ W,
                       const int*  __restrict__ itp) {
    if (blockIdx.x == 0 && threadIdx.x == 0) {
        int it = itp[0];
        double TAU   = 20.0 / log(64.0);
        double sigma = 64.0 * exp(-(double)it / TAU);
        g_sched[0] = (float)(2.0 * sigma * sigma);
        g_sched[1] = (float)(0.5 * exp(-(double)it / 20.0));
    }
    int warp = (blockIdx.x * blockDim.x + threadIdx.x) >> 5;
    int lane = threadIdx.x & 31;
    if (warp >= MN) return;
    const float* src = W + (size_t)warp * KDIM;
    float s = 0.f;
#pragma unroll
    for (int c = lane; c < KDIM; c += 32) { float v = src[c]; s += v * v; }
#pragma unroll
    for (int o = 16; o > 0; o >>= 1) s += __shfl_down_sync(0xffffffffu, s, o);
    if (lane == 0) g_wsq[warp] = s;
}

// ============================================================
// Kernel 1b: fp16 hi conversions of W and X (dist inputs)
// ============================================================
#define WPAIRS (MN * KDIM / 2)
#define XPAIRS (BSZ * KDIM / 2)
__global__ void ker_split(const float* __restrict__ W,
                          const float* __restrict__ X) {
    int idx = blockIdx.x * 256 + threadIdx.x;
    const float* src;
    __half* dhi;
    int p;
    if (idx < WPAIRS) {
        src = W; dhi = g_whi; p = idx;
    } else if (idx < WPAIRS + XPAIRS) {
        src = X; dhi = g_xhi; p = idx - WPAIRS;
    } else return;
    float2 v = *(const float2*)(src + (size_t)p * 2);
    *(__half2*)(dhi + (size_t)p * 2) =
        __halves2half2(__float2half_rn(v.x), __float2half_rn(v.y));
}

// ============================================================
// Kernel 1c: X -> transposed split-bf16 (numer inputs)
// ============================================================
__global__ void ker_prep(const float* __restrict__ X) {
    __shared__ float t[64][65];
    int bt = blockIdx.x;
    int dt = blockIdx.y;
    int tid = threadIdx.x;
#pragma unroll
    for (int s = 0; s < 16; s++) {
        int e = tid + 256 * s;
        int b = e >> 6, d = e & 63;
        t[b][d] = X[(size_t)(bt * 64 + b) * KDIM + dt * 64 + d];
    }
    __syncthreads();
#pragma unroll
    for (int s = 0; s < 8; s++) {
        int p = tid + 256 * s;
        int d = p >> 5, bp = p & 31;
        float a0 = t[bp * 2][d], a1 = t[bp * 2 + 1][d];
        __nv_bfloat16 h0 = __float2bfloat16_rn(a0);
        __nv_bfloat16 h1 = __float2bfloat16_rn(a1);
        __nv_bfloat16 l0 = __float2bfloat16_rn(a0 - __bfloat162float(h0));
        __nv_bfloat16 l1 = __float2bfloat16_rn(a1 - __bfloat162float(h1));
        size_t idx = (size_t)(dt * 64 + d) * BSZ + bt * 64 + bp * 2;
        *(uint32_t*)((char*)g_xthi + idx * 2) = pk2(h0, h1);
        *(uint32_t*)((char*)g_xtlo + idx * 2) = pk2(l0, l1);
    }
}

// ============================================================
// Kernel 2: approx distance GEMM (hh-only fp16 HMMA) + top-2.
// 512 thr = 16 warps: wb (32 b) x wj (32 j). W hi streamed
// 128j x 64k, cp.async 4-stage pipeline, one sync per iter.
// z = wsq[j] - 2*dot_hh (monotone in dist up to split error);
// exact fp32 fixup of the <=4 candidates happens in ker_fix.
// ============================================================
#define XS_STRIDE 528                        // 512 data + 16 pad
#define OFF_WBUF  (128 * XS_STRIDE)          // 67584
#define WROW      144                        // 128 data + 16 pad
#define WSTAGE    (128 * WROW)               // 18432
#define DIST_SMEM (OFF_WBUF + 4 * WSTAGE)    // 141312

__device__ __forceinline__ void dist_prefetch(uint32_t sbase, int ci,
                                              int jbase, int tid) {
    int jt = ci >> 2, kc = ci & 3;
    uint32_t dbuf = sbase + OFF_WBUF + (uint32_t)(ci & 3) * WSTAGE;
    size_t gro = ((size_t)(jbase + jt * 128)) * KDIM + kc * 64;
#pragma unroll
    for (int t = 0; t < 2; t++) {
        int i = tid + 512 * t;               // 1024 16B segs
        int r = i >> 3, s = i & 7;
        cpa16(dbuf + r * WROW + s * 16,
              (const char*)(g_whi + gro + (size_t)r * KDIM) + s * 16);
    }
}

__global__ void __launch_bounds__(512, 1)
ker_dist_mma() {
    char* base = (char*)sm;
    uint32_t sbase = smem_u32(base);
    const int tid  = threadIdx.x;
    const int lane = tid & 31;
    const int wid  = tid >> 5;
    const int wb   = wid >> 2;        // 0..3 -> 32 b
    const int wj   = wid & 3;         // 0..3 -> 32 j
    const int g    = lane >> 2;
    const int c2   = (lane & 3) * 2;
    const int b0   = blockIdx.x * 128;
    const int half = blockIdx.y;
    const int jbase = half * 8192;

    const int la15 = lane & 15;
    const int laKA = (lane >> 4) << 4;
    const int laRB = (lane & 7) + ((lane >> 4) << 3);
    const int laKB = ((lane >> 3) & 1) << 4;

    // ---- load X tile (hi fp16), 128 rows x 512B ----
#pragma unroll
    for (int t = 0; t < 8; t++) {
        int i = tid + 512 * t;
        int r = i >> 5, s = i & 31;
        *(uint4*)(base + r * XS_STRIDE + s * 16) =
            *(const uint4*)((const char*)(g_xhi + (size_t)(b0 + r) * KDIM) + s * 16);
    }

    float z1[4], z2[4];
    int   j1[4], j2[4];
#pragma unroll
    for (int i = 0; i < 4; i++) { z1[i] = z2[i] = FLT_MAX; j1[i] = j2[i] = MN; }

    dist_prefetch(sbase, 0, jbase, tid);
    CPA_COMMIT();
    dist_prefetch(sbase, 1, jbase, tid);
    CPA_COMMIT();
    dist_prefetch(sbase, 2, jbase, tid);
    CPA_COMMIT();

    float acc[2][4][4];

    for (int ci = 0; ci < 256; ci++) {
        const int jt = ci >> 2, kc = ci & 3;

        CPA_WAIT2();         // group ci complete
        __syncthreads();     // visible to all; all done with buffer (ci-1)&3
        if (ci + 3 < 256) {
            dist_prefetch(sbase, ci + 3, jbase, tid);
            CPA_COMMIT();
        }

        if (kc == 0) {
#pragma unroll
            for (int bt = 0; bt < 2; bt++)
#pragma unroll
                for (int nt = 0; nt < 4; nt++)
#pragma unroll
                    for (int r = 0; r < 4; r++) acc[bt][nt][r] = 0.f;
        }

        const uint32_t wboff = sbase + OFF_WBUF + (uint32_t)(ci & 3) * WSTAGE;
#pragma unroll
        for (int ks = 0; ks < 4; ks++) {
            uint32_t ah[2][4];
            const int kbX = (kc * 64 + ks * 16) * 2 + laKA;
#pragma unroll
            for (int bt = 0; bt < 2; bt++) {
                uint32_t ra = sbase + (wb * 32 + bt * 16 + la15) * XS_STRIDE + kbX;
                ldsm_x4(ah[bt][0], ah[bt][1], ah[bt][2], ah[bt][3], ra);
            }
            uint32_t bh[2][4];
            const int kbW = ks * 32 + laKB;
#pragma unroll
            for (int ntp = 0; ntp < 2; ntp++) {
                uint32_t rb = wboff + (wj * 32 + ntp * 16 + laRB) * WROW + kbW;
                ldsm_x4(bh[ntp][0], bh[ntp][1], bh[ntp][2], bh[ntp][3], rb);
            }
#pragma unroll
            for (int ntp = 0; ntp < 2; ntp++)
#pragma unroll
                for (int bt = 0; bt < 2; bt++) {
                    mma_f16(acc[bt][ntp*2],   ah[bt][0], ah[bt][1], ah[bt][2], ah[bt][3], bh[ntp][0], bh[ntp][1]);
                    mma_f16(acc[bt][ntp*2+1], ah[bt][0], ah[bt][1], ah[bt][2], ah[bt][3], bh[ntp][2], bh[ntp][3]);
                }
        }

        if (kc == 3) {
            const int j0 = jt * 128 + wj * 32;
#pragma unroll
            for (int nt = 0; nt < 4; nt++) {
                int jg = j0 + nt * 8 + c2;
                float w0 = g_wsq[jbase + jg];
                float w1 = g_wsq[jbase + jg + 1];
#pragma unroll
                for (int bt = 0; bt < 2; bt++) {
                    float zv[2][2];
                    zv[0][0] = fmaf(-2.f, acc[bt][nt][0], w0);
                    zv[0][1] = fmaf(-2.f, acc[bt][nt][1], w1);
                    zv[1][0] = fmaf(-2.f, acc[bt][nt][2], w0);
                    zv[1][1] = fmaf(-2.f, acc[bt][nt][3], w1);
#pragma unroll
                    for (int h = 0; h < 2; h++) {
                        int s = bt * 2 + h;
#pragma unroll
                        for (int q = 0; q < 2; q++) {
                            float z = zv[h][q];
                            int jq = jg + q;
                            if (z < z1[s]) {
                                z2[s] = z1[s]; j2[s] = j1[s];
                                z1[s] = z;     j1[s] = jq;
                            } else if (z < z2[s]) {
                                z2[s] = z; j2[s] = jq;
                            }
                        }
                    }
                }
            }
        }
    }

    // ---- cross-lane top-2 merge (c bits: xor 1, 2) ----
#pragma unroll
    for (int i = 0; i < 4; i++) {
#pragma unroll
        for (int off = 1; off <= 2; off <<= 1) {
            float oz1 = __shfl_xor_sync(0xffffffffu, z1[i], off);
            int   oj1 = __shfl_xor_sync(0xffffffffu, j1[i], off);
            float oz2 = __shfl_xor_sync(0xffffffffu, z2[i], off);
            int   oj2 = __shfl_xor_sync(0xffffffffu, j2[i], off);
            top2_merge(z1[i], j1[i], z2[i], j2[i], oz1, oj1, oz2, oj2);
        }
    }

    // ---- cross-warp top-2 merge via smem (reuse W region) ----
    __syncthreads();
    float* sz1 = (float*)(base + OFF_WBUF);
    int*   sj1 = (int*)(base + OFF_WBUF + 2048);
    float* sz2 = (float*)(base + OFF_WBUF + 4096);
    int*   sj2 = (int*)(base + OFF_WBUF + 6144);
    if ((lane & 3) == 0) {
#pragma unroll
        for (int i = 0; i < 4; i++) {
            int bt = i >> 1, h = i & 1;
            int row = wb * 32 + bt * 16 + g + 8 * h;
            sz1[row * 4 + wj] = z1[i];
            sj1[row * 4 + wj] = j1[i];
            sz2[row * 4 + wj] = z2[i];
            sj2[row * 4 + wj] = j2[i];
        }
    }
    __syncthreads();
    if (tid < 128) {
        float a1 = sz1[tid * 4], a2 = sz2[tid * 4];
        int   i1 = sj1[tid * 4], i2 = sj2[tid * 4];
        for (int t = 1; t < 4; t++)
            top2_merge(a1, i1, a2, i2,
                       sz1[tid * 4 + t], sj1[tid * 4 + t],
                       sz2[tid * 4 + t], sj2[tid * 4 + t]);
        int gb = half * BSZ + b0 + tid;
        g_cz[gb * 2]     = a1;
        g_cj[gb * 2]     = jbase + i1;
        g_cz[gb * 2 + 1] = a2;
        g_cj[gb * 2 + 1] = jbase + i2;
    }
}

// ============================================================
// Kernel 2b: exact fp32 re-evaluation of <=4 BMU candidates.
// One warp per b. z = wsq[j] - 2*dot(x,w) in fp32; lowest-j ties.
// ============================================================
__global__ void ker_fix(const float* __restrict__ X,
                        const float* __restrict__ W) {
    int b    = blockIdx.x * 8 + (threadIdx.x >> 5);
    int lane = threadIdx.x & 31;

    int cand[4];
    cand[0] = g_cj[b * 2];
    cand[1] = g_cj[b * 2 + 1];
    cand[2] = g_cj[(BSZ + b) * 2];
    cand[3] = g_cj[(BSZ + b) * 2 + 1];

    const float* xb = X + (size_t)b * KDIM;
    float x[8];
#pragma unroll
    for (int t = 0; t < 8; t++) x[t] = xb[lane * 8 + t];

    float bestz = FLT_MAX;
    int   bestj = MN;
#pragma unroll
    for (int c = 0; c < 4; c++) {
        int j = cand[c];
        const float* wj = W + (size_t)j * KDIM;
        float s = 0.f;
#pragma unroll
        for (int t = 0; t < 8; t++) s += x[t] * wj[lane * 8 + t];
#pragma unroll
        for (int o = 16; o > 0; o >>= 1) s += __shfl_down_sync(0xffffffffu, s, o);
        if (lane == 0) {
            float z = fmaf(-2.f, s, g_wsq[j]);
            if (z < bestz || (z == bestz && j < bestj)) { bestz = z; bestj = j; }
        }
    }
    if (lane == 0) g_bmu[b] = bestj;
}

// ============================================================
// Kernel 3: neighborhood factors from exact BMU
// ============================================================
__global__ void ker_pxpy() {
    int i = blockIdx.x;
    float d  = g_sched[0];
    float lr = g_sched[1];
    float fi = (float)i;
    for (int b = threadIdx.x; b < BSZ; b += 256) {
        int bmu = g_bmu[b];
        float dr = fi - (float)(bmu >> 7);
        float dc = fi - (float)(bmu & 127);
        g_pxT[(size_t)i * BSZ + b] = expf(-(dr * dr) / d);
        g_pyT[(size_t)i * BSZ + b] = lr * expf(-(dc * dc) / d);
    }
}

// ============================================================
// Kernel 4: numer (split-bf16 HMMA, ldmatrix) + fused denom.
// (unchanged from R8 — 77% of mma.sync floor)
// ============================================================
#define N_ROW    144
#define N_ALO    (128 * N_ROW)
#define N_ABUF   (2 * N_ALO)
#define N_XLO    (256 * N_ROW)
#define N_XBUF   (2 * N_XLO)
#define OFF_DSUM 0
#define OFF_A0   512
#define OFF_X0   (OFF_A0 + 2 * N_ABUF)
#define NUMER_SMEM (OFF_X0 + 2 * N_XBUF)

__global__ void __launch_bounds__(512, 1)
ker_numer_tc(const float* __restrict__ Wold, float* __restrict__ OUT) {
    char* base = (char*)sm;
    uint32_t sbase = smem_u32(base);
    float* dsum = (float*)(base + OFF_DSUM);

    const int tid  = threadIdx.x;
    const int wid  = tid >> 5;
    const int lane = tid & 31;
    const int m    = blockIdx.x;

    const int n0 = (wid >> 2) * 32;
    const int d0 = (wid & 3) * 64;
    const int g  = lane >> 2;
    const int c2 = (lane & 3) * 2;

    const int la15 = lane & 15;
    const int laKA = (lane >> 4) << 4;
    const int laRB = (lane & 7) + ((lane >> 4) << 3);
    const int laKB = ((lane >> 3) & 1) << 4;

    if (tid < 128) dsum[tid] = 0.f;

    float acc[2][8][4];
#pragma unroll
    for (int mt = 0; mt < 2; mt++)
#pragma unroll
        for (int nt = 0; nt < 8; nt++)
#pragma unroll
            for (int r = 0; r < 4; r++) acc[mt][nt][r] = 0.f;

    const float* pxm = g_pxT + (size_t)m * BSZ;
    const int bg = tid & 7;
    const int nrow = tid >> 3;
    float dden[2] = {0.f, 0.f};

#define NUMER_XPREF(ch) do {                                                   \
        int b0c = (ch) * 64;                                                   \
        uint32_t xb = sbase + OFF_X0 + (uint32_t)((ch) & 1) * N_XBUF;          \
        _Pragma("unroll")                                                      \
        for (int t = 0; t < 4; t++) {                                          \
            int i = tid + 512 * t;                                             \
            int r = i >> 3, s = i & 7;                                         \
            size_t go = ((size_t)r * BSZ + b0c + s * 8) * 2;                   \
            cpa16(xb + r * N_ROW + s * 16, (const char*)g_xthi + go);          \
            cpa16(xb + N_XLO + r * N_ROW + s * 16, (const char*)g_xtlo + go);  \
        }                                                                      \
    } while (0)

#define NUMER_ASTAGE(ch) do {                                                  \
        int b0c = (ch) * 64;                                                   \
        uint32_t ab = (uint32_t)(OFF_A0 + ((ch) & 1) * N_ABUF);                \
        float4 px0 = *(const float4*)(pxm + b0c + bg * 8);                     \
        float4 px1 = *(const float4*)(pxm + b0c + bg * 8 + 4);                 \
        float pxv[8] = {px0.x, px0.y, px0.z, px0.w,                            \
                        px1.x, px1.y, px1.z, px1.w};                           \
        _Pragma("unroll")                                                      \
        for (int s = 0; s < 2; s++) {                                          \
            int n = nrow + 64 * s;                                             \
            const float* py = g_pyT + (size_t)n * BSZ + b0c + bg * 8;          \
            float4 p0 = *(const float4*)py;                                    \
            float4 p1 = *(const float4*)(py + 4);                              \
            float a[8] = {pxv[0]*p0.x, pxv[1]*p0.y, pxv[2]*p0.z, pxv[3]*p0.w,  \
                          pxv[4]*p1.x, pxv[5]*p1.y, pxv[6]*p1.z, pxv[7]*p1.w}; \
            float ssum = 0.f;                                                  \
            __nv_bfloat16 h[8], l[8];                                          \
            _Pragma("unroll")                                                  \
            for (int j = 0; j < 8; j++) {                                      \
                ssum += a[j];                                                  \
                h[j] = __float2bfloat16_rn(a[j]);                              \
                l[j] = __float2bfloat16_rn(a[j] - __bfloat162float(h[j]));     \
            }                                                                  \
            dden[s] += ssum;                                                   \
            uint4 hv = make_uint4(pk2(h[0],h[1]), pk2(h[2],h[3]),              \
                                  pk2(h[4],h[5]), pk2(h[6],h[7]));             \
            uint4 lv = make_uint4(pk2(l[0],l[1]), pk2(l[2],l[3]),              \
                                  pk2(l[4],l[5]), pk2(l[6],l[7]));             \
            uint32_t so = n * N_ROW + bg * 16;                                 \
            *(uint4*)(base + ab + so) = hv;                                    \
            *(uint4*)(base + ab + N_ALO + so) = lv;                            \
        }                                                                      \
    } while (0)

    NUMER_ASTAGE(0);
    NUMER_XPREF(0);
    CPA_COMMIT();

    for (int ch = 0; ch < 128; ch++) {
        CPA_WAIT0();
        __syncthreads();

        if (ch + 1 < 128) {
            NUMER_XPREF(ch + 1);
            CPA_COMMIT();
            NUMER_ASTAGE(ch + 1);
        }

        const uint32_t abase = sbase + OFF_A0 + (uint32_t)(ch & 1) * N_ABUF;
        const uint32_t xbase = sbase + OFF_X0 + (uint32_t)(ch & 1) * N_XBUF;
#pragma unroll
        for (int ks = 0; ks < 4; ks++) {
            uint32_t ah[2][4], al[2][4];
            const int kbA = ks * 32 + laKA;
#pragma unroll
            for (int bt = 0; bt < 2; bt++) {
                uint32_t ra = abase + (n0 + bt * 16 + la15) * N_ROW + kbA;
                ldsm_x4(ah[bt][0], ah[bt][1], ah[bt][2], ah[bt][3], ra);
                ldsm_x4(al[bt][0], al[bt][1], al[bt][2], al[bt][3], ra + N_ALO);
            }
            const int kbB = ks * 32 + laKB;
#pragma unroll
            for (int h2 = 0; h2 < 2; h2++) {
                uint32_t bh[2][4], bl[2][4];
#pragma unroll
                for (int p = 0; p < 2; p++) {
                    int ntp = h2 * 2 + p;
                    uint32_t rb = xbase + (d0 + ntp * 16 + laRB) * N_ROW + kbB;
                    ldsm_x4(bh[p][0], bh[p][1], bh[p][2], bh[p][3], rb);
                    ldsm_x4(bl[p][0], bl[p][1], bl[p][2], bl[p][3], rb + N_XLO);
                }
#pragma unroll
                for (int p = 0; p < 2; p++)
#pragma unroll
                    for (int bt = 0; bt < 2; bt++) {
                        int nt = (h2 * 2 + p) * 2;
                        mma_bf16(acc[bt][nt],   ah[bt][0], ah[bt][1], ah[bt][2], ah[bt][3], bh[p][0], bh[p][1]);
                        mma_bf16(acc[bt][nt+1], ah[bt][0], ah[bt][1], ah[bt][2], ah[bt][3], bh[p][2], bh[p][3]);
                    }
#pragma unroll
                for (int p = 0; p < 2; p++)
#pragma unroll
                    for (int bt = 0; bt < 2; bt++) {
                        int nt = (h2 * 2 + p) * 2;
                        mma_bf16(acc[bt][nt],   ah[bt][0], ah[bt][1], ah[bt][2], ah[bt][3], bl[p][0], bl[p][1]);
                        mma_bf16(acc[bt][nt+1], ah[bt][0], ah[bt][1], ah[bt][2], ah[bt][3], bl[p][2], bl[p][3]);
                    }
#pragma unroll
                for (int p = 0; p < 2; p++)
#pragma unroll
                    for (int bt = 0; bt < 2; bt++) {
                        int nt = (h2 * 2 + p) * 2;
                        mma_bf16(acc[bt][nt],   al[bt][0], al[bt][1], al[bt][2], al[bt][3], bh[p][0], bh[p][1]);
                        mma_bf16(acc[bt][nt+1], al[bt][0], al[bt][1], al[bt][2], al[bt][3], bh[p][2], bh[p][3]);
                    }
            }
        }
    }

    __syncthreads();
#pragma unroll
    for (int s = 0; s < 2; s++)
        atomicAdd(&dsum[nrow + 64 * s], dden[s]);
    __syncthreads();

#pragma unroll
    for (int mt = 0; mt < 2; mt++) {
#pragma unroll
        for (int gg = 0; gg < 2; gg++) {
            int n = n0 + mt * 16 + g + gg * 8;
            float den = dsum[n];
            size_t rb = ((size_t)(m * 128 + n)) * KDIM;
#pragma unroll
            for (int nt = 0; nt < 8; nt++) {
                int dcol = d0 + nt * 8 + c2;
                float v0 = acc[mt][nt][gg * 2];
                float v1 = acc[mt][nt][gg * 2 + 1];
                float2 o;
                if (den != 0.f) {
                    o.x = v0 / den; o.y = v1 / den;
                } else {
                    o.x = Wold[rb + dcol]; o.y = Wold[rb + dcol + 1];
                }
                *(float2*)(OUT + rb + dcol) = o;
            }
        }
    }
}

// ============================================================
extern "C" void kernel_launch(void* const* d_in, const int* in_sizes, int n_in,
                              void* d_out, int out_size) {
    (void)in_sizes; (void)n_in; (void)out_size;
    const float* data    = (const float*)d_in[0];
    const float* weights = (const float*)d_in[1];
    const int*   itp     = (const int*)d_in[2];
    float*       out     = (float*)d_out;

    cudaFuncSetAttribute(ker_dist_mma, cudaFuncAttributeMaxDynamicSharedMemorySize,
                         DIST_SMEM);
    cudaFuncSetAttribute(ker_numer_tc, cudaFuncAttributeMaxDynamicSharedMemorySize,
                         NUMER_SMEM);

    ker_sq<<<MN / 8, 256>>>(weights, itp);
    ker_split<<<(WPAIRS + XPAIRS) / 256, 256>>>(weights, data);
    ker_prep<<<dim3(BSZ / 64, KDIM / 64), 256>>>(data);
    ker_dist_mma<<<dim3(64, 2), 512, DIST_SMEM>>>();
    ker_fix<<<BSZ / 8, 256>>>(data, weights);
    ker_pxpy<<<128, 256>>>();
    ker_numer_tc<<<128, 512, NUMER_SMEM>>>(weights, out);
}

// round 10
// speedup vs baseline: 1.8694x; 1.2539x over previous
#include <cuda_runtime.h>
#include <cuda_bf16.h>
#include <cuda_fp16.h>
#include <math.h>
#include <stdint.h>
#include <float.h>

#define BSZ   8192
#define MDIM  128
#define NDIM  128
#define KDIM  256
#define MN    16384

// -------- device scratch --------
__device__ float g_wsq[MN];
__device__ float g_pxT[MDIM * BSZ];    // [m][b]
__device__ float g_pyT[NDIM * BSZ];    // [n][b]
__device__ float g_sched[2];           // [0] = 2*sigma^2, [1] = lr
__device__ __align__(16) __half g_xthi[KDIM * BSZ];  // X^T hi (fp16) [d][b] (numer)
__device__ __align__(16) __half g_xtlo[KDIM * BSZ];  // X^T lo (fp16) [d][b] (numer)
__device__ __align__(16) __half g_whi[MN * KDIM];    // W hi (fp16) [j][k] (dist)
__device__ __align__(16) __half g_xhi[BSZ * KDIM];   // X hi (fp16) [b][k] (dist)
__device__ float g_cz[2 * BSZ * 2];    // top-2 approx scores per (half, b)
__device__ int   g_cj[2 * BSZ * 2];    // top-2 candidate j (global)
__device__ int   g_bmu[BSZ];

extern __shared__ float sm[];

__device__ __forceinline__ uint32_t smem_u32(const void* p) {
    uint32_t a;
    asm("{ .reg .u64 t; cvta.to.shared.u64 t, %1; cvt.u32.u64 %0, t; }"
        : "=r"(a) : "l"(p));
    return a;
}
__device__ __forceinline__ uint32_t pk2h(__half a, __half b) {
    __half2 t = __halves2half2(a, b);
    return *reinterpret_cast<uint32_t*>(&t);
}
__device__ __forceinline__ void mma_f16(float* d,
                                        uint32_t a0, uint32_t a1,
                                        uint32_t a2, uint32_t a3,
                                        uint32_t b0, uint32_t b1) {
    asm volatile(
        "mma.sync.aligned.m16n8k16.row.col.f32.f16.f16.f32 "
        "{%0,%1,%2,%3}, {%4,%5,%6,%7}, {%8,%9}, {%0,%1,%2,%3};"
        : "+f"(d[0]), "+f"(d[1]), "+f"(d[2]), "+f"(d[3])
        : "r"(a0), "r"(a1), "r"(a2), "r"(a3), "r"(b0), "r"(b1));
}
__device__ __forceinline__ void ldsm_x4(uint32_t& r0, uint32_t& r1,
                                        uint32_t& r2, uint32_t& r3,
                                        uint32_t addr) {
    asm volatile("ldmatrix.sync.aligned.m8n8.x4.shared.b16 {%0,%1,%2,%3}, [%4];"
                 : "=r"(r0), "=r"(r1), "=r"(r2), "=r"(r3) : "r"(addr));
}
__device__ __forceinline__ void cpa16(uint32_t saddr, const void* g) {
    asm volatile("cp.async.cg.shared.global [%0], [%1], 16;"
                 :: "r"(saddr), "l"(g));
}
#define CPA_COMMIT() asm volatile("cp.async.commit_group;" ::: "memory")
#define CPA_WAIT0()  asm volatile("cp.async.wait_group 0;" ::: "memory")
#define CPA_WAIT1()  asm volatile("cp.async.wait_group 1;" ::: "memory")

// top-2 merge of sorted pairs
__device__ __forceinline__ void top2_merge(float& z1, int& j1, float& z2, int& j2,
                                           float oz1, int oj1, float oz2, int oj2) {
    bool b1 = (oz1 < z1) || (oz1 == z1 && oj1 < j1);
    if (b1) {
        bool b2 = (z1 < oz2) || (z1 == oz2 && j1 < oj2);
        z2 = b2 ? z1 : oz2; j2 = b2 ? j1 : oj2;
        z1 = oz1; j1 = oj1;
    } else {
        bool b2 = (oz1 < z2) || (oz1 == z2 && oj1 < j2);
        z2 = b2 ? oz1 : z2; j2 = b2 ? oj1 : j2;
    }
}

// ============================================================
// Kernel 1: wsq + schedule
// ============================================================
__global__ void ker_sq(const float* __restrict__ W,
                       const int*  __restrict__ itp) {
    if (blockIdx.x == 0 && threadIdx.x == 0) {
        int it = itp[0];
        double TAU   = 20.0 / log(64.0);
        double sigma = 64.0 * exp(-(double)it / TAU);
        g_sched[0] = (float)(2.0 * sigma * sigma);
        g_sched[1] = (float)(0.5 * exp(-(double)it / 20.0));
    }
    int warp = (blockIdx.x * blockDim.x + threadIdx.x) >> 5;
    int lane = threadIdx.x & 31;
    if (warp >= MN) return;
    const float* src = W + (size_t)warp * KDIM;
    float s = 0.f;
#pragma unroll
    for (int c = lane; c < KDIM; c += 32) { float v = src[c]; s += v * v; }
#pragma unroll
    for (int o = 16; o > 0; o >>= 1) s += __shfl_down_sync(0xffffffffu, s, o);
    if (lane == 0) g_wsq[warp] = s;
}

// ============================================================
// Kernel 1b: fp16 hi conversions of W and X (dist inputs)
// ============================================================
#define WPAIRS (MN * KDIM / 2)
#define XPAIRS (BSZ * KDIM / 2)
__global__ void ker_split(const float* __restrict__ W,
                          const float* __restrict__ X) {
    int idx = blockIdx.x * 256 + threadIdx.x;
    const float* src;
    __half* dhi;
    int p;
    if (idx < WPAIRS) {
        src = W; dhi = g_whi; p = idx;
    } else if (idx < WPAIRS + XPAIRS) {
        src = X; dhi = g_xhi; p = idx - WPAIRS;
    } else return;
    float2 v = *(const float2*)(src + (size_t)p * 2);
    *(__half2*)(dhi + (size_t)p * 2) =
        __halves2half2(__float2half_rn(v.x), __float2half_rn(v.y));
}

// ============================================================
// Kernel 1c: X -> transposed split-fp16 (numer inputs)
// ============================================================
__global__ void ker_prep(const float* __restrict__ X) {
    __shared__ float t[64][65];
    int bt = blockIdx.x;
    int dt = blockIdx.y;
    int tid = threadIdx.x;
#pragma unroll
    for (int s = 0; s < 16; s++) {
        int e = tid + 256 * s;
        int b = e >> 6, d = e & 63;
        t[b][d] = X[(size_t)(bt * 64 + b) * KDIM + dt * 64 + d];
    }
    __syncthreads();
#pragma unroll
    for (int s = 0; s < 8; s++) {
        int p = tid + 256 * s;
        int d = p >> 5, bp = p & 31;
        float a0 = t[bp * 2][d], a1 = t[bp * 2 + 1][d];
        __half h0 = __float2half_rn(a0);
        __half h1 = __float2half_rn(a1);
        __half l0 = __float2half_rn(a0 - __half2float(h0));
        __half l1 = __float2half_rn(a1 - __half2float(h1));
        size_t idx = (size_t)(dt * 64 + d) * BSZ + bt * 64 + bp * 2;
        *(uint32_t*)((char*)g_xthi + idx * 2) = pk2h(h0, h1);
        *(uint32_t*)((char*)g_xtlo + idx * 2) = pk2h(l0, l1);
    }
}

// ============================================================
// Kernel 2: approx distance GEMM (hh-only fp16 HMMA) + top-2.
// 512 thr = 16 warps: wb (32 b) x wj (32 j). W hi streamed
// 128j x 128k per chunk, 3-stage cp.async ring, 1 sync/iter.
// Exact fp32 fixup of candidates in ker_fix.
// ============================================================
#define XS_STRIDE 528                        // 512 data + 16 pad
#define OFF_WBUF  (128 * XS_STRIDE)          // 67584
#define WROW      272                        // 256 data + 16 pad (17==1 mod 8)
#define WSTAGE    (128 * WROW)               // 34816
#define DIST_SMEM (OFF_WBUF + 3 * WSTAGE)    // 172032

__device__ __forceinline__ void dist_prefetch(uint32_t sbase, int ci,
                                              int jbase, int tid) {
    int jt = ci >> 1, kc = ci & 1;
    uint32_t dbuf = sbase + OFF_WBUF + (uint32_t)(ci % 3) * WSTAGE;
    size_t gro = ((size_t)(jbase + jt * 128)) * KDIM + kc * 128;
#pragma unroll
    for (int t = 0; t < 4; t++) {
        int i = tid + 512 * t;               // 2048 16B segs
        int r = i >> 4, s = i & 15;
        cpa16(dbuf + r * WROW + s * 16,
              (const char*)(g_whi + gro + (size_t)r * KDIM) + s * 16);
    }
}

__global__ void __launch_bounds__(512, 1)
ker_dist_mma() {
    char* base = (char*)sm;
    uint32_t sbase = smem_u32(base);
    const int tid  = threadIdx.x;
    const int lane = tid & 31;
    const int wid  = tid >> 5;
    const int wb   = wid >> 2;        // 0..3 -> 32 b
    const int wj   = wid & 3;         // 0..3 -> 32 j
    const int g    = lane >> 2;
    const int c2   = (lane & 3) * 2;
    const int b0   = blockIdx.x * 128;
    const int half = blockIdx.y;
    const int jbase = half * 8192;

    const int la15 = lane & 15;
    const int laKA = (lane >> 4) << 4;
    const int laRB = (lane & 7) + ((lane >> 4) << 3);
    const int laKB = ((lane >> 3) & 1) << 4;

    // ---- load X tile (hi fp16), 128 rows x 512B ----
#pragma unroll
    for (int t = 0; t < 8; t++) {
        int i = tid + 512 * t;
        int r = i >> 5, s = i & 31;
        *(uint4*)(base + r * XS_STRIDE + s * 16) =
            *(const uint4*)((const char*)(g_xhi + (size_t)(b0 + r) * KDIM) + s * 16);
    }

    float z1[4], z2[4];
    int   j1[4], j2[4];
#pragma unroll
    for (int i = 0; i < 4; i++) { z1[i] = z2[i] = FLT_MAX; j1[i] = j2[i] = MN; }

    dist_prefetch(sbase, 0, jbase, tid);
    CPA_COMMIT();
    dist_prefetch(sbase, 1, jbase, tid);
    CPA_COMMIT();

    float acc[2][4][4];

    for (int ci = 0; ci < 128; ci++) {
        const int jt = ci >> 1, kc = ci & 1;

        CPA_WAIT1();         // group ci complete (only ci+1 may remain)
        __syncthreads();     // visible everywhere; all done with prior reads
        if (ci + 2 < 128) {
            dist_prefetch(sbase, ci + 2, jbase, tid);
            CPA_COMMIT();
        }

        if (kc == 0) {
#pragma unroll
            for (int bt = 0; bt < 2; bt++)
#pragma unroll
                for (int nt = 0; nt < 4; nt++)
#pragma unroll
                    for (int r = 0; r < 4; r++) acc[bt][nt][r] = 0.f;
        }

        const uint32_t wboff = sbase + OFF_WBUF + (uint32_t)(ci % 3) * WSTAGE;
#pragma unroll
        for (int ks = 0; ks < 8; ks++) {
            uint32_t ah[2][4];
            const int kbX = (kc * 128 + ks * 16) * 2 + laKA;
#pragma unroll
            for (int bt = 0; bt < 2; bt++) {
                uint32_t ra = sbase + (wb * 32 + bt * 16 + la15) * XS_STRIDE + kbX;
                ldsm_x4(ah[bt][0], ah[bt][1], ah[bt][2], ah[bt][3], ra);
            }
            uint32_t bh[2][4];
            const int kbW = ks * 32 + laKB;
#pragma unroll
            for (int ntp = 0; ntp < 2; ntp++) {
                uint32_t rb = wboff + (wj * 32 + ntp * 16 + laRB) * WROW + kbW;
                ldsm_x4(bh[ntp][0], bh[ntp][1], bh[ntp][2], bh[ntp][3], rb);
            }
#pragma unroll
            for (int ntp = 0; ntp < 2; ntp++)
#pragma unroll
                for (int bt = 0; bt < 2; bt++) {
                    mma_f16(acc[bt][ntp*2],   ah[bt][0], ah[bt][1], ah[bt][2], ah[bt][3], bh[ntp][0], bh[ntp][1]);
                    mma_f16(acc[bt][ntp*2+1], ah[bt][0], ah[bt][1], ah[bt][2], ah[bt][3], bh[ntp][2], bh[ntp][3]);
                }
        }

        if (kc == 1) {
            const int j0 = jt * 128 + wj * 32;
#pragma unroll
            for (int nt = 0; nt < 4; nt++) {
                int jg = j0 + nt * 8 + c2;
                float w0 = g_wsq[jbase + jg];
                float w1 = g_wsq[jbase + jg + 1];
#pragma unroll
                for (int bt = 0; bt < 2; bt++) {
                    float zv[2][2];
                    zv[0][0] = fmaf(-2.f, acc[bt][nt][0], w0);
                    zv[0][1] = fmaf(-2.f, acc[bt][nt][1], w1);
                    zv[1][0] = fmaf(-2.f, acc[bt][nt][2], w0);
                    zv[1][1] = fmaf(-2.f, acc[bt][nt][3], w1);
#pragma unroll
                    for (int h = 0; h < 2; h++) {
                        int s = bt * 2 + h;
#pragma unroll
                        for (int q = 0; q < 2; q++) {
                            float z = zv[h][q];
                            int jq = jg + q;
                            if (z < z1[s]) {
                                z2[s] = z1[s]; j2[s] = j1[s];
                                z1[s] = z;     j1[s] = jq;
                            } else if (z < z2[s]) {
                                z2[s] = z; j2[s] = jq;
                            }
                        }
                    }
                }
            }
        }
    }

    // ---- cross-lane top-2 merge ----
#pragma unroll
    for (int i = 0; i < 4; i++) {
#pragma unroll
        for (int off = 1; off <= 2; off <<= 1) {
            float oz1 = __shfl_xor_sync(0xffffffffu, z1[i], off);
            int   oj1 = __shfl_xor_sync(0xffffffffu, j1[i], off);
            float oz2 = __shfl_xor_sync(0xffffffffu, z2[i], off);
            int   oj2 = __shfl_xor_sync(0xffffffffu, j2[i], off);
            top2_merge(z1[i], j1[i], z2[i], j2[i], oz1, oj1, oz2, oj2);
        }
    }

    // ---- cross-warp top-2 merge via smem ----
    __syncthreads();
    float* sz1 = (float*)(base + OFF_WBUF);
    int*   sj1 = (int*)(base + OFF_WBUF + 2048);
    float* sz2 = (float*)(base + OFF_WBUF + 4096);
    int*   sj2 = (int*)(base + OFF_WBUF + 6144);
    if ((lane & 3) == 0) {
#pragma unroll
        for (int i = 0; i < 4; i++) {
            int bt = i >> 1, h = i & 1;
            int row = wb * 32 + bt * 16 + g + 8 * h;
            sz1[row * 4 + wj] = z1[i];
            sj1[row * 4 + wj] = j1[i];
            sz2[row * 4 + wj] = z2[i];
            sj2[row * 4 + wj] = j2[i];
        }
    }
    __syncthreads();
    if (tid < 128) {
        float a1 = sz1[tid * 4], a2 = sz2[tid * 4];
        int   i1 = sj1[tid * 4], i2 = sj2[tid * 4];
        for (int t = 1; t < 4; t++)
            top2_merge(a1, i1, a2, i2,
                       sz1[tid * 4 + t], sj1[tid * 4 + t],
                       sz2[tid * 4 + t], sj2[tid * 4 + t]);
        int gb = half * BSZ + b0 + tid;
        g_cz[gb * 2]     = a1;
        g_cj[gb * 2]     = jbase + i1;
        g_cz[gb * 2 + 1] = a2;
        g_cj[gb * 2 + 1] = jbase + i2;
    }
}

// ============================================================
// Kernel 2b: exact fp32 re-evaluation of <=4 BMU candidates.
// ============================================================
__global__ void ker_fix(const float* __restrict__ X,
                        const float* __restrict__ W) {
    int b    = blockIdx.x * 8 + (threadIdx.x >> 5);
    int lane = threadIdx.x & 31;

    int cand[4];
    cand[0] = g_cj[b * 2];
    cand[1] = g_cj[b * 2 + 1];
    cand[2] = g_cj[(BSZ + b) * 2];
    cand[3] = g_cj[(BSZ + b) * 2 + 1];

    const float* xb = X + (size_t)b * KDIM;
    float x[8];
#pragma unroll
    for (int t = 0; t < 8; t++) x[t] = xb[lane * 8 + t];

    float bestz = FLT_MAX;
    int   bestj = MN;
#pragma unroll
    for (int c = 0; c < 4; c++) {
        int j = cand[c];
        const float* wj = W + (size_t)j * KDIM;
        float s = 0.f;
#pragma unroll
        for (int t = 0; t < 8; t++) s += x[t] * wj[lane * 8 + t];
#pragma unroll
        for (int o = 16; o > 0; o >>= 1) s += __shfl_down_sync(0xffffffffu, s, o);
        if (lane == 0) {
            float z = fmaf(-2.f, s, g_wsq[j]);
            if (z < bestz || (z == bestz && j < bestj)) { bestz = z; bestj = j; }
        }
    }
    if (lane == 0) g_bmu[b] = bestj;
}

// ============================================================
// Kernel 3: neighborhood factors from exact BMU
// ============================================================
__global__ void ker_pxpy() {
    int i = blockIdx.x;
    float d  = g_sched[0];
    float lr = g_sched[1];
    float fi = (float)i;
    for (int b = threadIdx.x; b < BSZ; b += 256) {
        int bmu = g_bmu[b];
        float dr = fi - (float)(bmu >> 7);
        float dc = fi - (float)(bmu & 127);
        g_pxT[(size_t)i * BSZ + b] = expf(-(dr * dr) / d);
        g_pyT[(size_t)i * BSZ + b] = lr * expf(-(dc * dc) / d);
    }
}

// ============================================================
// Kernel 4: numer (fp16 HMMA: A single-precision-rounded fp16,
// X^T split hi/lo -> 2 terms) + fused denom (sums the SAME
// rounded A for consistency). Double-buffered, 1 sync/iter.
// ============================================================
#define N_ROW    144
#define N_ABUF   (128 * N_ROW)               // 18432 (single A array)
#define N_XLO    (256 * N_ROW)               // 36864
#define N_XBUF   (2 * N_XLO)                 // 73728
#define OFF_DSUM 0
#define OFF_A0   512
#define OFF_X0   (OFF_A0 + 2 * N_ABUF)       // 37376
#define NUMER_SMEM (OFF_X0 + 2 * N_XBUF)     // 184832

__global__ void __launch_bounds__(512, 1)
ker_numer_tc(const float* __restrict__ Wold, float* __restrict__ OUT) {
    char* base = (char*)sm;
    uint32_t sbase = smem_u32(base);
    float* dsum = (float*)(base + OFF_DSUM);

    const int tid  = threadIdx.x;
    const int wid  = tid >> 5;
    const int lane = tid & 31;
    const int m    = blockIdx.x;

    const int n0 = (wid >> 2) * 32;
    const int d0 = (wid & 3) * 64;
    const int g  = lane >> 2;
    const int c2 = (lane & 3) * 2;

    const int la15 = lane & 15;
    const int laKA = (lane >> 4) << 4;
    const int laRB = (lane & 7) + ((lane >> 4) << 3);
    const int laKB = ((lane >> 3) & 1) << 4;

    if (tid < 128) dsum[tid] = 0.f;

    float acc[2][8][4];
#pragma unroll
    for (int mt = 0; mt < 2; mt++)
#pragma unroll
        for (int nt = 0; nt < 8; nt++)
#pragma unroll
            for (int r = 0; r < 4; r++) acc[mt][nt][r] = 0.f;

    const float* pxm = g_pxT + (size_t)m * BSZ;
    const int bg = tid & 7;
    const int nrow = tid >> 3;
    float dden[2] = {0.f, 0.f};

#define NUMER_XPREF(ch) do {                                                   \
        int b0c = (ch) * 64;                                                   \
        uint32_t xb = sbase + OFF_X0 + (uint32_t)((ch) & 1) * N_XBUF;          \
        _Pragma("unroll")                                                      \
        for (int t = 0; t < 4; t++) {                                          \
            int i = tid + 512 * t;                                             \
            int r = i >> 3, s = i & 7;                                         \
            size_t go = ((size_t)r * BSZ + b0c + s * 8) * 2;                   \
            cpa16(xb + r * N_ROW + s * 16, (const char*)g_xthi + go);          \
            cpa16(xb + N_XLO + r * N_ROW + s * 16, (const char*)g_xtlo + go);  \
        }                                                                      \
    } while (0)

#define NUMER_ASTAGE(ch) do {                                                  \
        int b0c = (ch) * 64;                                                   \
        uint32_t ab = (uint32_t)(OFF_A0 + ((ch) & 1) * N_ABUF);                \
        float4 px0 = *(const float4*)(pxm + b0c + bg * 8);                     \
        float4 px1 = *(const float4*)(pxm + b0c + bg * 8 + 4);                 \
        float pxv[8] = {px0.x, px0.y, px0.z, px0.w,                            \
                        px1.x, px1.y, px1.z, px1.w};                           \
        _Pragma("unroll")                                                      \
        for (int s = 0; s < 2; s++) {                                          \
            int n = nrow + 64 * s;                                             \
            const float* py = g_pyT + (size_t)n * BSZ + b0c + bg * 8;          \
            float4 p0 = *(const float4*)py;                                    \
            float4 p1 = *(const float4*)(py + 4);                              \
            float a[8] = {pxv[0]*p0.x, pxv[1]*p0.y, pxv[2]*p0.z, pxv[3]*p0.w,  \
                          pxv[4]*p1.x, pxv[5]*p1.y, pxv[6]*p1.z, pxv[7]*p1.w}; \
            float ssum = 0.f;                                                  \
            __half h[8];                                                       \
            _Pragma("unroll")                                                  \
            for (int j = 0; j < 8; j++) {                                      \
                h[j] = __float2half_rn(a[j]);                                  \
                ssum += __half2float(h[j]);                                    \
            }                                                                  \
            dden[s] += ssum;                                                   \
            uint4 hv = make_uint4(pk2h(h[0],h[1]), pk2h(h[2],h[3]),            \
                                  pk2h(h[4],h[5]), pk2h(h[6],h[7]));           \
            *(uint4*)(base + ab + n * N_ROW + bg * 16) = hv;                   \
        }                                                                      \
    } while (0)

    NUMER_ASTAGE(0);
    NUMER_XPREF(0);
    CPA_COMMIT();

    for (int ch = 0; ch < 128; ch++) {
        CPA_WAIT0();
        __syncthreads();

        if (ch + 1 < 128) {
            NUMER_XPREF(ch + 1);
            CPA_COMMIT();
            NUMER_ASTAGE(ch + 1);
        }

        const uint32_t abase = sbase + OFF_A0 + (uint32_t)(ch & 1) * N_ABUF;
        const uint32_t xbase = sbase + OFF_X0 + (uint32_t)(ch & 1) * N_XBUF;
#pragma unroll
        for (int ks = 0; ks < 4; ks++) {
            uint32_t ah[2][4];
            const int kbA = ks * 32 + laKA;
#pragma unroll
            for (int bt = 0; bt < 2; bt++) {
                uint32_t ra = abase + (n0 + bt * 16 + la15) * N_ROW + kbA;
                ldsm_x4(ah[bt][0], ah[bt][1], ah[bt][2], ah[bt][3], ra);
            }
            const int kbB = ks * 32 + laKB;
#pragma unroll
            for (int h2 = 0; h2 < 2; h2++) {
                uint32_t bh[2][4], bl[2][4];
#pragma unroll
                for (int p = 0; p < 2; p++) {
                    int ntp = h2 * 2 + p;
                    uint32_t rb = xbase + (d0 + ntp * 16 + laRB) * N_ROW + kbB;
                    ldsm_x4(bh[p][0], bh[p][1], bh[p][2], bh[p][3], rb);
                    ldsm_x4(bl[p][0], bl[p][1], bl[p][2], bl[p][3], rb + N_XLO);
                }
                // term-major: a*x_hi then a*x_lo (acc reuse distance 8)
#pragma unroll
                for (int p = 0; p < 2; p++)
#pragma unroll
                    for (int bt = 0; bt < 2; bt++) {
                        int nt = (h2 * 2 + p) * 2;
                        mma_f16(acc[bt][nt],   ah[bt][0], ah[bt][1], ah[bt][2], ah[bt][3], bh[p][0], bh[p][1]);
                        mma_f16(acc[bt][nt+1], ah[bt][0], ah[bt][1], ah[bt][2], ah[bt][3], bh[p][2], bh[p][3]);
                    }
#pragma unroll
                for (int p = 0; p < 2; p++)
#pragma unroll
                    for (int bt = 0; bt < 2; bt++) {
                        int nt = (h2 * 2 + p) * 2;
                        mma_f16(acc[bt][nt],   ah[bt][0], ah[bt][1], ah[bt][2], ah[bt][3], bl[p][0], bl[p][1]);
                        mma_f16(acc[bt][nt+1], ah[bt][0], ah[bt][1], ah[bt][2], ah[bt][3], bl[p][2], bl[p][3]);
                    }
            }
        }
    }

    __syncthreads();
#pragma unroll
    for (int s = 0; s < 2; s++)
        atomicAdd(&dsum[nrow + 64 * s], dden[s]);
    __syncthreads();

#pragma unroll
    for (int mt = 0; mt < 2; mt++) {
#pragma unroll
        for (int gg = 0; gg < 2; gg++) {
            int n = n0 + mt * 16 + g + gg * 8;
            float den = dsum[n];
            size_t rb = ((size_t)(m * 128 + n)) * KDIM;
#pragma unroll
            for (int nt = 0; nt < 8; nt++) {
                int dcol = d0 + nt * 8 + c2;
                float v0 = acc[mt][nt][gg * 2];
                float v1 = acc[mt][nt][gg * 2 + 1];
                float2 o;
                if (den != 0.f) {
                    o.x = v0 / den; o.y = v1 / den;
                } else {
                    o.x = Wold[rb + dcol]; o.y = Wold[rb + dcol + 1];
                }
                *(float2*)(OUT + rb + dcol) = o;
            }
        }
    }
}

// ============================================================
extern "C" void kernel_launch(void* const* d_in, const int* in_sizes, int n_in,
                              void* d_out, int out_size) {
    (void)in_sizes; (void)n_in; (void)out_size;
    const float* data    = (const float*)d_in[0];
    const float* weights = (const float*)d_in[1];
    const int*   itp     = (const int*)d_in[2];
    float*       out     = (float*)d_out;

    cudaFuncSetAttribute(ker_dist_mma, cudaFuncAttributeMaxDynamicSharedMemorySize,
                         DIST_SMEM);
    cudaFuncSetAttribute(ker_numer_tc, cudaFuncAttributeMaxDynamicSharedMemorySize,
                         NUMER_SMEM);

    ker_sq<<<MN / 8, 256>>>(weights, itp);
    ker_split<<<(WPAIRS + XPAIRS) / 256, 256>>>(weights, data);
    ker_prep<<<dim3(BSZ / 64, KDIM / 64), 256>>>(data);
    ker_dist_mma<<<dim3(64, 2), 512, DIST_SMEM>>>();
    ker_fix<<<BSZ / 8, 256>>>(data, weights);
    ker_pxpy<<<128, 256>>>();
    ker_numer_tc<<<128, 512, NUMER_SMEM>>>(weights, out);
}

// round 11
// speedup vs baseline: 1.9837x; 1.0611x over previous
#include <cuda_runtime.h>
#include <cuda_bf16.h>
#include <cuda_fp16.h>
#include <math.h>
#include <stdint.h>
#include <float.h>

#define BSZ   8192
#define MDIM  128
#define NDIM  128
#define KDIM  256
#define MN    16384

// -------- device scratch --------
__device__ __align__(16) float g_wsq[MN];
__device__ float g_sched[2];           // [0] = 2*sigma^2, [1] = lr
__device__ __align__(16) __half g_pxTh[MDIM * BSZ];  // px fp16 [m][b]
__device__ __align__(16) __half g_pyTh[NDIM * BSZ];  // py*lr fp16 [n][b]
__device__ __align__(16) __half g_xthi[KDIM * BSZ];  // X^T hi (fp16) [d][b]
__device__ __align__(16) __half g_xtlo[KDIM * BSZ];  // X^T lo (fp16) [d][b]
__device__ __align__(16) __half g_whi[MN * KDIM];    // W hi (fp16) [j][k]
__device__ __align__(16) __half g_xhi[BSZ * KDIM];   // X hi (fp16) [b][k]
__device__ int   g_cj[2 * BSZ * 2];    // top-2 candidate j per (half, b)
__device__ int   g_bmu[BSZ];

extern __shared__ float sm[];

__device__ __forceinline__ uint32_t smem_u32(const void* p) {
    uint32_t a;
    asm("{ .reg .u64 t; cvta.to.shared.u64 t, %1; cvt.u32.u64 %0, t; }"
        : "=r"(a) : "l"(p));
    return a;
}
__device__ __forceinline__ uint32_t pk2h(__half a, __half b) {
    __half2 t = __halves2half2(a, b);
    return *reinterpret_cast<uint32_t*>(&t);
}
__device__ __forceinline__ void mma_f16(float* d,
                                        uint32_t a0, uint32_t a1,
                                        uint32_t a2, uint32_t a3,
                                        uint32_t b0, uint32_t b1) {
    asm volatile(
        "mma.sync.aligned.m16n8k16.row.col.f32.f16.f16.f32 "
        "{%0,%1,%2,%3}, {%4,%5,%6,%7}, {%8,%9}, {%0,%1,%2,%3};"
        : "+f"(d[0]), "+f"(d[1]), "+f"(d[2]), "+f"(d[3])
        : "r"(a0), "r"(a1), "r"(a2), "r"(a3), "r"(b0), "r"(b1));
}
__device__ __forceinline__ void ldsm_x4(uint32_t& r0, uint32_t& r1,
                                        uint32_t& r2, uint32_t& r3,
                                        uint32_t addr) {
    asm volatile("ldmatrix.sync.aligned.m8n8.x4.shared.b16 {%0,%1,%2,%3}, [%4];"
                 : "=r"(r0), "=r"(r1), "=r"(r2), "=r"(r3) : "r"(addr));
}
__device__ __forceinline__ void cpa16(uint32_t saddr, const void* g) {
    asm volatile("cp.async.cg.shared.global [%0], [%1], 16;"
                 :: "r"(saddr), "l"(g));
}
#define CPA_COMMIT() asm volatile("cp.async.commit_group;" ::: "memory")
#define CPA_WAIT0()  asm volatile("cp.async.wait_group 0;" ::: "memory")
#define CPA_WAIT1()  asm volatile("cp.async.wait_group 1;" ::: "memory")

__device__ __forceinline__ void t2_ins(float z, int j,
                                       float& z1, int& j1, float& z2, int& j2) {
    if (z < z1) { z2 = z1; j2 = j1; z1 = z; j1 = j; }
    else if (z < z2) { z2 = z; j2 = j; }
}
__device__ __forceinline__ void top2_merge(float& z1, int& j1, float& z2, int& j2,
                                           float oz1, int oj1, float oz2, int oj2) {
    bool b1 = (oz1 < z1) || (oz1 == z1 && oj1 < j1);
    if (b1) {
        bool b2 = (z1 < oz2) || (z1 == oz2 && j1 < oj2);
        z2 = b2 ? z1 : oz2; j2 = b2 ? j1 : oj2;
        z1 = oz1; j1 = oj1;
    } else {
        bool b2 = (oz1 < z2) || (oz1 == z2 && oj1 < j2);
        z2 = b2 ? oz1 : z2; j2 = b2 ? oj1 : j2;
    }
}

// ============================================================
// Kernel 1: wsq + schedule
// ============================================================
__global__ void ker_sq(const float* __restrict__ W,
                       const int*  __restrict__ itp) {
    if (blockIdx.x == 0 && threadIdx.x == 0) {
        int it = itp[0];
        double TAU   = 20.0 / log(64.0);
        double sigma = 64.0 * exp(-(double)it / TAU);
        g_sched[0] = (float)(2.0 * sigma * sigma);
        g_sched[1] = (float)(0.5 * exp(-(double)it / 20.0));
    }
    int warp = (blockIdx.x * blockDim.x + threadIdx.x) >> 5;
    int lane = threadIdx.x & 31;
    if (warp >= MN) return;
    const float* src = W + (size_t)warp * KDIM;
    float s = 0.f;
#pragma unroll
    for (int c = lane; c < KDIM; c += 32) { float v = src[c]; s += v * v; }
#pragma unroll
    for (int o = 16; o > 0; o >>= 1) s += __shfl_down_sync(0xffffffffu, s, o);
    if (lane == 0) g_wsq[warp] = s;
}

// ============================================================
// Kernel 1b: fp16 hi conversions of W and X (dist inputs)
// ============================================================
#define WPAIRS (MN * KDIM / 2)
#define XPAIRS (BSZ * KDIM / 2)
__global__ void ker_split(const float* __restrict__ W,
                          const float* __restrict__ X) {
    int idx = blockIdx.x * 256 + threadIdx.x;
    const float* src;
    __half* dhi;
    int p;
    if (idx < WPAIRS) {
        src = W; dhi = g_whi; p = idx;
    } else if (idx < WPAIRS + XPAIRS) {
        src = X; dhi = g_xhi; p = idx - WPAIRS;
    } else return;
    float2 v = *(const float2*)(src + (size_t)p * 2);
    *(__half2*)(dhi + (size_t)p * 2) =
        __halves2half2(__float2half_rn(v.x), __float2half_rn(v.y));
}

// ============================================================
// Kernel 1c: X -> transposed split-fp16 (numer inputs)
// ============================================================
__global__ void ker_prep(const float* __restrict__ X) {
    __shared__ float t[64][65];
    int bt = blockIdx.x;
    int dt = blockIdx.y;
    int tid = threadIdx.x;
#pragma unroll
    for (int s = 0; s < 16; s++) {
        int e = tid + 256 * s;
        int b = e >> 6, d = e & 63;
        t[b][d] = X[(size_t)(bt * 64 + b) * KDIM + dt * 64 + d];
    }
    __syncthreads();
#pragma unroll
    for (int s = 0; s < 8; s++) {
        int p = tid + 256 * s;
        int d = p >> 5, bp = p & 31;
        float a0 = t[bp * 2][d], a1 = t[bp * 2 + 1][d];
        __half h0 = __float2half_rn(a0);
        __half h1 = __float2half_rn(a1);
        __half l0 = __float2half_rn(a0 - __half2float(h0));
        __half l1 = __float2half_rn(a1 - __half2float(h1));
        size_t idx = (size_t)(dt * 64 + d) * BSZ + bt * 64 + bp * 2;
        *(uint32_t*)((char*)g_xthi + idx * 2) = pk2h(h0, h1);
        *(uint32_t*)((char*)g_xtlo + idx * 2) = pk2h(l0, l1);
    }
}

// ============================================================
// Kernel 2: approx distance GEMM (hh-only fp16 HMMA) + top-2.
// wsq cached in SMEM; cheap-skip top-2 insert in epilogue.
// ============================================================
#define XS_STRIDE 528
#define OFF_WBUF  (128 * XS_STRIDE)          // 67584
#define WROW      272
#define WSTAGE    (128 * WROW)               // 34816
#define OFF_WSQ   (OFF_WBUF + 3 * WSTAGE)    // 172032
#define DIST_SMEM (OFF_WSQ + 32768)          // 204800

__device__ __forceinline__ void dist_prefetch(uint32_t sbase, int ci,
                                              int jbase, int tid) {
    int jt = ci >> 1, kc = ci & 1;
    uint32_t dbuf = sbase + OFF_WBUF + (uint32_t)(ci % 3) * WSTAGE;
    size_t gro = ((size_t)(jbase + jt * 128)) * KDIM + kc * 128;
#pragma unroll
    for (int t = 0; t < 4; t++) {
        int i = tid + 512 * t;
        int r = i >> 4, s = i & 15;
        cpa16(dbuf + r * WROW + s * 16,
              (const char*)(g_whi + gro + (size_t)r * KDIM) + s * 16);
    }
}

__global__ void __launch_bounds__(512, 1)
ker_dist_mma() {
    char* base = (char*)sm;
    uint32_t sbase = smem_u32(base);
    const int tid  = threadIdx.x;
    const int lane = tid & 31;
    const int wid  = tid >> 5;
    const int wb   = wid >> 2;
    const int wj   = wid & 3;
    const int g    = lane >> 2;
    const int c2   = (lane & 3) * 2;
    const int b0   = blockIdx.x * 128;
    const int half = blockIdx.y;
    const int jbase = half * 8192;

    const int la15 = lane & 15;
    const int laKA = (lane >> 4) << 4;
    const int laRB = (lane & 7) + ((lane >> 4) << 3);
    const int laKB = ((lane >> 3) & 1) << 4;

    // ---- load X tile (hi fp16) + wsq slice into smem ----
#pragma unroll
    for (int t = 0; t < 8; t++) {
        int i = tid + 512 * t;
        int r = i >> 5, s = i & 31;
        *(uint4*)(base + r * XS_STRIDE + s * 16) =
            *(const uint4*)((const char*)(g_xhi + (size_t)(b0 + r) * KDIM) + s * 16);
    }
#pragma unroll
    for (int t = 0; t < 4; t++) {
        int i = tid + 512 * t;                // 2048 16B segs = 32KB
        *(uint4*)(base + OFF_WSQ + i * 16) =
            *(const uint4*)((const char*)(g_wsq + jbase) + i * 16);
    }
    const float* swsq = (const float*)(base + OFF_WSQ);

    float z1[4], z2[4];
    int   j1[4], j2[4];
#pragma unroll
    for (int i = 0; i < 4; i++) { z1[i] = z2[i] = FLT_MAX; j1[i] = j2[i] = MN; }

    dist_prefetch(sbase, 0, jbase, tid);
    CPA_COMMIT();
    dist_prefetch(sbase, 1, jbase, tid);
    CPA_COMMIT();

    float acc[2][4][4];

    for (int ci = 0; ci < 128; ci++) {
        const int jt = ci >> 1, kc = ci & 1;

        CPA_WAIT1();
        __syncthreads();
        if (ci + 2 < 128) {
            dist_prefetch(sbase, ci + 2, jbase, tid);
            CPA_COMMIT();
        }

        if (kc == 0) {
#pragma unroll
            for (int bt = 0; bt < 2; bt++)
#pragma unroll
                for (int nt = 0; nt < 4; nt++)
#pragma unroll
                    for (int r = 0; r < 4; r++) acc[bt][nt][r] = 0.f;
        }

        const uint32_t wboff = sbase + OFF_WBUF + (uint32_t)(ci % 3) * WSTAGE;
#pragma unroll
        for (int ks = 0; ks < 8; ks++) {
            uint32_t ah[2][4];
            const int kbX = (kc * 128 + ks * 16) * 2 + laKA;
#pragma unroll
            for (int bt = 0; bt < 2; bt++) {
                uint32_t ra = sbase + (wb * 32 + bt * 16 + la15) * XS_STRIDE + kbX;
                ldsm_x4(ah[bt][0], ah[bt][1], ah[bt][2], ah[bt][3], ra);
            }
            uint32_t bh[2][4];
            const int kbW = ks * 32 + laKB;
#pragma unroll
            for (int ntp = 0; ntp < 2; ntp++) {
                uint32_t rb = wboff + (wj * 32 + ntp * 16 + laRB) * WROW + kbW;
                ldsm_x4(bh[ntp][0], bh[ntp][1], bh[ntp][2], bh[ntp][3], rb);
            }
#pragma unroll
            for (int ntp = 0; ntp < 2; ntp++)
#pragma unroll
                for (int bt = 0; bt < 2; bt++) {
                    mma_f16(acc[bt][ntp*2],   ah[bt][0], ah[bt][1], ah[bt][2], ah[bt][3], bh[ntp][0], bh[ntp][1]);
                    mma_f16(acc[bt][ntp*2+1], ah[bt][0], ah[bt][1], ah[bt][2], ah[bt][3], bh[ntp][2], bh[ntp][3]);
                }
        }

        if (kc == 1) {
            const int j0 = jt * 128 + wj * 32;
#pragma unroll
            for (int nt = 0; nt < 4; nt++) {
                int jg = j0 + nt * 8 + c2;
                float w0 = swsq[jg];
                float w1 = swsq[jg + 1];
#pragma unroll
                for (int bt = 0; bt < 2; bt++) {
                    float za0 = fmaf(-2.f, acc[bt][nt][0], w0);
                    float zb0 = fmaf(-2.f, acc[bt][nt][1], w1);
                    float za1 = fmaf(-2.f, acc[bt][nt][2], w0);
                    float zb1 = fmaf(-2.f, acc[bt][nt][3], w1);
                    int s0 = bt * 2, s1 = bt * 2 + 1;
                    if (fminf(za0, zb0) < z2[s0]) {
                        t2_ins(za0, jg,     z1[s0], j1[s0], z2[s0], j2[s0]);
                        t2_ins(zb0, jg + 1, z1[s0], j1[s0], z2[s0], j2[s0]);
                    }
                    if (fminf(za1, zb1) < z2[s1]) {
                        t2_ins(za1, jg,     z1[s1], j1[s1], z2[s1], j2[s1]);
                        t2_ins(zb1, jg + 1, z1[s1], j1[s1], z2[s1], j2[s1]);
                    }
                }
            }
        }
    }

    // ---- cross-lane top-2 merge ----
#pragma unroll
    for (int i = 0; i < 4; i++) {
#pragma unroll
        for (int off = 1; off <= 2; off <<= 1) {
            float oz1 = __shfl_xor_sync(0xffffffffu, z1[i], off);
            int   oj1 = __shfl_xor_sync(0xffffffffu, j1[i], off);
            float oz2 = __shfl_xor_sync(0xffffffffu, z2[i], off);
            int   oj2 = __shfl_xor_sync(0xffffffffu, j2[i], off);
            top2_merge(z1[i], j1[i], z2[i], j2[i], oz1, oj1, oz2, oj2);
        }
    }

    // ---- cross-warp top-2 merge via smem ----
    __syncthreads();
    float* sz1 = (float*)(base + OFF_WBUF);
    int*   sj1 = (int*)(base + OFF_WBUF + 2048);
    float* sz2 = (float*)(base + OFF_WBUF + 4096);
    int*   sj2 = (int*)(base + OFF_WBUF + 6144);
    if ((lane & 3) == 0) {
#pragma unroll
        for (int i = 0; i < 4; i++) {
            int bt = i >> 1, h = i & 1;
            int row = wb * 32 + bt * 16 + g + 8 * h;
            sz1[row * 4 + wj] = z1[i];
            sj1[row * 4 + wj] = j1[i];
            sz2[row * 4 + wj] = z2[i];
            sj2[row * 4 + wj] = j2[i];
        }
    }
    __syncthreads();
    if (tid < 128) {
        float a1 = sz1[tid * 4], a2 = sz2[tid * 4];
        int   i1 = sj1[tid * 4], i2 = sj2[tid * 4];
        for (int t = 1; t < 4; t++)
            top2_merge(a1, i1, a2, i2,
                       sz1[tid * 4 + t], sj1[tid * 4 + t],
                       sz2[tid * 4 + t], sj2[tid * 4 + t]);
        int gb = half * BSZ + b0 + tid;
        g_cj[gb * 2]     = jbase + i1;
        g_cj[gb * 2 + 1] = jbase + i2;
    }
}

// ============================================================
// Kernel 2b: exact fp32 re-evaluation of <=4 BMU candidates.
// ============================================================
__global__ void ker_fix(const float* __restrict__ X,
                        const float* __restrict__ W) {
    int b    = blockIdx.x * 8 + (threadIdx.x >> 5);
    int lane = threadIdx.x & 31;

    int cand[4];
    cand[0] = g_cj[b * 2];
    cand[1] = g_cj[b * 2 + 1];
    cand[2] = g_cj[(BSZ + b) * 2];
    cand[3] = g_cj[(BSZ + b) * 2 + 1];

    const float* xb = X + (size_t)b * KDIM;
    float x[8];
#pragma unroll
    for (int t = 0; t < 8; t++) x[t] = xb[lane * 8 + t];

    float bestz = FLT_MAX;
    int   bestj = MN;
#pragma unroll
    for (int c = 0; c < 4; c++) {
        int j = cand[c];
        const float* wj = W + (size_t)j * KDIM;
        float s = 0.f;
#pragma unroll
        for (int t = 0; t < 8; t++) s += x[t] * wj[lane * 8 + t];
#pragma unroll
        for (int o = 16; o > 0; o >>= 1) s += __shfl_down_sync(0xffffffffu, s, o);
        if (lane == 0) {
            float z = fmaf(-2.f, s, g_wsq[j]);
            if (z < bestz || (z == bestz && j < bestj)) { bestz = z; bestj = j; }
        }
    }
    if (lane == 0) g_bmu[b] = bestj;
}

// ============================================================
// Kernel 3: neighborhood factors (fp16) from exact BMU
// ============================================================
__global__ void ker_pxpy() {
    int i = blockIdx.x;
    float d  = g_sched[0];
    float lr = g_sched[1];
    float fi = (float)i;
    for (int b = threadIdx.x; b < BSZ; b += 256) {
        int bmu = g_bmu[b];
        float dr = fi - (float)(bmu >> 7);
        float dc = fi - (float)(bmu & 127);
        g_pxTh[(size_t)i * BSZ + b] = __float2half_rn(expf(-(dr * dr) / d));
        g_pyTh[(size_t)i * BSZ + b] = __float2half_rn(lr * expf(-(dc * dc) / d));
    }
}

// ============================================================
// Kernel 4: numer (fp16 HMMA, 2 terms) + fused denom.
// px/py fp16 LDG issued BEFORE the MMA block (latency hidden);
// convert+STS after MMAs. X^T double-buffered via cp.async.
// ============================================================
#define N_ROW    144
#define N_ABUF   (128 * N_ROW)
#define N_XLO    (256 * N_ROW)
#define N_XBUF   (2 * N_XLO)
#define OFF_DSUM 0
#define OFF_A0   512
#define OFF_X0   (OFF_A0 + 2 * N_ABUF)
#define NUMER_SMEM (OFF_X0 + 2 * N_XBUF)     // 184832

__global__ void __launch_bounds__(512, 1)
ker_numer_tc(const float* __restrict__ Wold, float* __restrict__ OUT) {
    char* base = (char*)sm;
    uint32_t sbase = smem_u32(base);
    float* dsum = (float*)(base + OFF_DSUM);

    const int tid  = threadIdx.x;
    const int wid  = tid >> 5;
    const int lane = tid & 31;
    const int m    = blockIdx.x;

    const int n0 = (wid >> 2) * 32;
    const int d0 = (wid & 3) * 64;
    const int g  = lane >> 2;
    const int c2 = (lane & 3) * 2;

    const int la15 = lane & 15;
    const int laKA = (lane >> 4) << 4;
    const int laRB = (lane & 7) + ((lane >> 4) << 3);
    const int laKB = ((lane >> 3) & 1) << 4;

    if (tid < 128) dsum[tid] = 0.f;

    float acc[2][8][4];
#pragma unroll
    for (int mt = 0; mt < 2; mt++)
#pragma unroll
        for (int nt = 0; nt < 8; nt++)
#pragma unroll
            for (int r = 0; r < 4; r++) acc[mt][nt][r] = 0.f;

    const int bg = tid & 7;
    const int nrow = tid >> 3;
    float dden[2] = {0.f, 0.f};

#define NUMER_XPREF(ch) do {                                                   \
        int b0c = (ch) * 64;                                                   \
        uint32_t xb = sbase + OFF_X0 + (uint32_t)((ch) & 1) * N_XBUF;          \
        _Pragma("unroll")                                                      \
        for (int t = 0; t < 4; t++) {                                          \
            int i = tid + 512 * t;                                             \
            int r = i >> 3, s = i & 7;                                         \
            size_t go = ((size_t)r * BSZ + b0c + s * 8) * 2;                   \
            cpa16(xb + r * N_ROW + s * 16, (const char*)g_xthi + go);          \
            cpa16(xb + N_XLO + r * N_ROW + s * 16, (const char*)g_xtlo + go);  \
        }                                                                      \
    } while (0)

#define NUMER_LDG(ch, pxv, py0, py1) do {                                      \
        size_t bo = (size_t)((ch) * 64 + bg * 8) * 2;                          \
        pxv = *(const uint4*)((const char*)(g_pxTh + (size_t)m * BSZ) + bo);   \
        py0 = *(const uint4*)((const char*)(g_pyTh + (size_t)nrow * BSZ) + bo);\
        py1 = *(const uint4*)((const char*)(g_pyTh + (size_t)(nrow + 64) * BSZ) + bo); \
    } while (0)

#define NUMER_CONVERT(ch, pxv, py0, py1) do {                                  \
        uint32_t ab = (uint32_t)(OFF_A0 + ((ch) & 1) * N_ABUF);                \
        __half2* pxh = (__half2*)&(pxv);                                       \
        float2 pf[4];                                                          \
        _Pragma("unroll")                                                      \
        for (int k = 0; k < 4; k++) pf[k] = __half22float2(pxh[k]);            \
        _Pragma("unroll")                                                      \
        for (int s = 0; s < 2; s++) {                                          \
            int n = nrow + 64 * s;                                             \
            uint4 pv = s ? (py1) : (py0);                                      \
            __half2* ph = (__half2*)&pv;                                       \
            float ssum = 0.f;                                                  \
            __half h[8];                                                       \
            _Pragma("unroll")                                                  \
            for (int k = 0; k < 4; k++) {                                      \
                float2 yf = __half22float2(ph[k]);                             \
                float a0 = pf[k].x * yf.x;                                     \
                float a1 = pf[k].y * yf.y;                                     \
                h[2*k]   = __float2half_rn(a0);                                \
                h[2*k+1] = __float2half_rn(a1);                                \
                ssum += __half2float(h[2*k]) + __half2float(h[2*k+1]);         \
            }                                                                  \
            dden[s] += ssum;                                                   \
            uint4 hv = make_uint4(pk2h(h[0],h[1]), pk2h(h[2],h[3]),            \
                                  pk2h(h[4],h[5]), pk2h(h[6],h[7]));           \
            *(uint4*)(base + ab + n * N_ROW + bg * 16) = hv;                   \
        }                                                                      \
    } while (0)

    // prologue: stage A(0), prefetch X(0)
    {
        uint4 pxv, py0, py1;
        NUMER_LDG(0, pxv, py0, py1);
        NUMER_CONVERT(0, pxv, py0, py1);
        NUMER_XPREF(0);
        CPA_COMMIT();
    }

    uint4 pxv, py0, py1;
    for (int ch = 0; ch < 128; ch++) {
        CPA_WAIT0();
        __syncthreads();

        const bool more = (ch + 1 < 128);
        if (more) {
            NUMER_XPREF(ch + 1);
            CPA_COMMIT();
            NUMER_LDG(ch + 1, pxv, py0, py1);   // issue loads; consumed after MMAs
        }

        const uint32_t abase = sbase + OFF_A0 + (uint32_t)(ch & 1) * N_ABUF;
        const uint32_t xbase = sbase + OFF_X0 + (uint32_t)(ch & 1) * N_XBUF;
#pragma unroll
        for (int ks = 0; ks < 4; ks++) {
            uint32_t ah[2][4];
            const int kbA = ks * 32 + laKA;
#pragma unroll
            for (int bt = 0; bt < 2; bt++) {
                uint32_t ra = abase + (n0 + bt * 16 + la15) * N_ROW + kbA;
                ldsm_x4(ah[bt][0], ah[bt][1], ah[bt][2], ah[bt][3], ra);
            }
            const int kbB = ks * 32 + laKB;
#pragma unroll
            for (int h2 = 0; h2 < 2; h2++) {
                uint32_t bh[2][4], bl[2][4];
#pragma unroll
                for (int p = 0; p < 2; p++) {
                    int ntp = h2 * 2 + p;
                    uint32_t rb = xbase + (d0 + ntp * 16 + laRB) * N_ROW + kbB;
                    ldsm_x4(bh[p][0], bh[p][1], bh[p][2], bh[p][3], rb);
                    ldsm_x4(bl[p][0], bl[p][1], bl[p][2], bl[p][3], rb + N_XLO);
                }
#pragma unroll
                for (int p = 0; p < 2; p++)
#pragma unroll
                    for (int bt = 0; bt < 2; bt++) {
                        int nt = (h2 * 2 + p) * 2;
                        mma_f16(acc[bt][nt],   ah[bt][0], ah[bt][1], ah[bt][2], ah[bt][3], bh[p][0], bh[p][1]);
                        mma_f16(acc[bt][nt+1], ah[bt][0], ah[bt][1], ah[bt][2], ah[bt][3], bh[p][2], bh[p][3]);
                    }
#pragma unroll
                for (int p = 0; p < 2; p++)
#pragma unroll
                    for (int bt = 0; bt < 2; bt++) {
                        int nt = (h2 * 2 + p) * 2;
                        mma_f16(acc[bt][nt],   ah[bt][0], ah[bt][1], ah[bt][2], ah[bt][3], bl[p][0], bl[p][1]);
                        mma_f16(acc[bt][nt+1], ah[bt][0], ah[bt][1], ah[bt][2], ah[bt][3], bl[p][2], bl[p][3]);
                    }
            }
        }

        if (more) NUMER_CONVERT(ch + 1, pxv, py0, py1);
    }

    __syncthreads();
#pragma unroll
    for (int s = 0; s < 2; s++)
        atomicAdd(&dsum[nrow + 64 * s], dden[s]);
    __syncthreads();

#pragma unroll
    for (int mt = 0; mt < 2; mt++) {
#pragma unroll
        for (int gg = 0; gg < 2; gg++) {
            int n = n0 + mt * 16 + g + gg * 8;
            float den = dsum[n];
            size_t rb = ((size_t)(m * 128 + n)) * KDIM;
#pragma unroll
            for (int nt = 0; nt < 8; nt++) {
                int dcol = d0 + nt * 8 + c2;
                float v0 = acc[mt][nt][gg * 2];
                float v1 = acc[mt][nt][gg * 2 + 1];
                float2 o;
                if (den != 0.f) {
                    o.x = v0 / den; o.y = v1 / den;
                } else {
                    o.x = Wold[rb + dcol]; o.y = Wold[rb + dcol + 1];
                }
                *(float2*)(OUT + rb + dcol) = o;
            }
        }
    }
}

// ============================================================
extern "C" void kernel_launch(void* const* d_in, const int* in_sizes, int n_in,
                              void* d_out, int out_size) {
    (void)in_sizes; (void)n_in; (void)out_size;
    const float* data    = (const float*)d_in[0];
    const float* weights = (const float*)d_in[1];
    const int*   itp     = (const int*)d_in[2];
    float*       out     = (float*)d_out;

    cudaFuncSetAttribute(ker_dist_mma, cudaFuncAttributeMaxDynamicSharedMemorySize,
                         DIST_SMEM);
    cudaFuncSetAttribute(ker_numer_tc, cudaFuncAttributeMaxDynamicSharedMemorySize,
                         NUMER_SMEM);

    ker_sq<<<MN / 8, 256>>>(weights, itp);
    ker_split<<<(WPAIRS + XPAIRS) / 256, 256>>>(weights, data);
    ker_prep<<<dim3(BSZ / 64, KDIM / 64), 256>>>(data);
    ker_dist_mma<<<dim3(64, 2), 512, DIST_SMEM>>>();
    ker_fix<<<BSZ / 8, 256>>>(data, weights);
    ker_pxpy<<<128, 256>>>();
    ker_numer_tc<<<128, 512, NUMER_SMEM>>>(weights, out);
}

// round 12
// speedup vs baseline: 2.0071x; 1.0118x over previous
#include <cuda_runtime.h>
#include <cuda_bf16.h>
#include <cuda_fp16.h>
#include <math.h>
#include <stdint.h>
#include <float.h>

#define BSZ   8192
#define MDIM  128
#define NDIM  128
#define KDIM  256
#define MN    16384

// -------- device scratch --------
__device__ __align__(16) float g_wsq[MN];
__device__ float g_sched[2];           // [0] = 2*sigma^2, [1] = lr
__device__ __align__(16) __half g_pxTh[MDIM * BSZ];  // px fp16 [m][b]
__device__ __align__(16) __half g_pyTh[NDIM * BSZ];  // py*lr fp16 [n][b]
__device__ __align__(16) __half g_xthi[KDIM * BSZ];  // X^T hi (fp16) [d][b]
__device__ __align__(16) __half g_xtlo[KDIM * BSZ];  // X^T lo (fp16) [d][b]
__device__ __align__(16) __half g_whi[MN * KDIM];    // W hi (fp16) [j][k]
__device__ __align__(16) __half g_xhi[BSZ * KDIM];   // X hi (fp16) [b][k]
__device__ int   g_cj[4 * BSZ * 2];    // top-2 candidate j per (quarter, b)
__device__ int   g_bmu[BSZ];

extern __shared__ float sm[];

__device__ __forceinline__ uint32_t smem_u32(const void* p) {
    uint32_t a;
    asm("{ .reg .u64 t; cvta.to.shared.u64 t, %1; cvt.u32.u64 %0, t; }"
        : "=r"(a) : "l"(p));
    return a;
}
__device__ __forceinline__ uint32_t pk2h(__half a, __half b) {
    __half2 t = __halves2half2(a, b);
    return *reinterpret_cast<uint32_t*>(&t);
}
__device__ __forceinline__ void mma_f16(float* d,
                                        uint32_t a0, uint32_t a1,
                                        uint32_t a2, uint32_t a3,
                                        uint32_t b0, uint32_t b1) {
    asm volatile(
        "mma.sync.aligned.m16n8k16.row.col.f32.f16.f16.f32 "
        "{%0,%1,%2,%3}, {%4,%5,%6,%7}, {%8,%9}, {%0,%1,%2,%3};"
        : "+f"(d[0]), "+f"(d[1]), "+f"(d[2]), "+f"(d[3])
        : "r"(a0), "r"(a1), "r"(a2), "r"(a3), "r"(b0), "r"(b1));
}
__device__ __forceinline__ void ldsm_x4(uint32_t& r0, uint32_t& r1,
                                        uint32_t& r2, uint32_t& r3,
                                        uint32_t addr) {
    asm volatile("ldmatrix.sync.aligned.m8n8.x4.shared.b16 {%0,%1,%2,%3}, [%4];"
                 : "=r"(r0), "=r"(r1), "=r"(r2), "=r"(r3) : "r"(addr));
}
__device__ __forceinline__ void cpa16(uint32_t saddr, const void* g) {
    asm volatile("cp.async.cg.shared.global [%0], [%1], 16;"
                 :: "r"(saddr), "l"(g));
}
#define CPA_COMMIT() asm volatile("cp.async.commit_group;" ::: "memory")
#define CPA_WAIT0()  asm volatile("cp.async.wait_group 0;" ::: "memory")

__device__ __forceinline__ void t2_ins(float z, int j,
                                       float& z1, int& j1, float& z2, int& j2) {
    if (z < z1) { z2 = z1; j2 = j1; z1 = z; j1 = j; }
    else if (z < z2) { z2 = z; j2 = j; }
}
__device__ __forceinline__ void top2_merge(float& z1, int& j1, float& z2, int& j2,
                                           float oz1, int oj1, float oz2, int oj2) {
    bool b1 = (oz1 < z1) || (oz1 == z1 && oj1 < j1);
    if (b1) {
        bool b2 = (z1 < oz2) || (z1 == oz2 && j1 < oj2);
        z2 = b2 ? z1 : oz2; j2 = b2 ? j1 : oj2;
        z1 = oz1; j1 = oj1;
    } else {
        bool b2 = (oz1 < z2) || (oz1 == z2 && oj1 < j2);
        z2 = b2 ? oz1 : z2; j2 = b2 ? oj1 : j2;
    }
}

// ============================================================
// Kernel 1: wsq + schedule
// ============================================================
__global__ void ker_sq(const float* __restrict__ W,
                       const int*  __restrict__ itp) {
    if (blockIdx.x == 0 && threadIdx.x == 0) {
        int it = itp[0];
        double TAU   = 20.0 / log(64.0);
        double sigma = 64.0 * exp(-(double)it / TAU);
        g_sched[0] = (float)(2.0 * sigma * sigma);
        g_sched[1] = (float)(0.5 * exp(-(double)it / 20.0));
    }
    int warp = (blockIdx.x * blockDim.x + threadIdx.x) >> 5;
    int lane = threadIdx.x & 31;
    if (warp >= MN) return;
    const float* src = W + (size_t)warp * KDIM;
    float s = 0.f;
#pragma unroll
    for (int c = lane; c < KDIM; c += 32) { float v = src[c]; s += v * v; }
#pragma unroll
    for (int o = 16; o > 0; o >>= 1) s += __shfl_down_sync(0xffffffffu, s, o);
    if (lane == 0) g_wsq[warp] = s;
}

// ============================================================
// Kernel 1b: fp16 hi conversions of W and X (dist inputs)
// ============================================================
#define WPAIRS (MN * KDIM / 2)
#define XPAIRS (BSZ * KDIM / 2)
__global__ void ker_split(const float* __restrict__ W,
                          const float* __restrict__ X) {
    int idx = blockIdx.x * 256 + threadIdx.x;
    const float* src;
    __half* dhi;
    int p;
    if (idx < WPAIRS) {
        src = W; dhi = g_whi; p = idx;
    } else if (idx < WPAIRS + XPAIRS) {
        src = X; dhi = g_xhi; p = idx - WPAIRS;
    } else return;
    float2 v = *(const float2*)(src + (size_t)p * 2);
    *(__half2*)(dhi + (size_t)p * 2) =
        __halves2half2(__float2half_rn(v.x), __float2half_rn(v.y));
}

// ============================================================
// Kernel 1c: X -> transposed split-fp16 (numer inputs)
// ============================================================
__global__ void ker_prep(const float* __restrict__ X) {
    __shared__ float t[64][65];
    int bt = blockIdx.x;
    int dt = blockIdx.y;
    int tid = threadIdx.x;
#pragma unroll
    for (int s = 0; s < 16; s++) {
        int e = tid + 256 * s;
        int b = e >> 6, d = e & 63;
        t[b][d] = X[(size_t)(bt * 64 + b) * KDIM + dt * 64 + d];
    }
    __syncthreads();
#pragma unroll
    for (int s = 0; s < 8; s++) {
        int p = tid + 256 * s;
        int d = p >> 5, bp = p & 31;
        float a0 = t[bp * 2][d], a1 = t[bp * 2 + 1][d];
        __half h0 = __float2half_rn(a0);
        __half h1 = __float2half_rn(a1);
        __half l0 = __float2half_rn(a0 - __half2float(h0));
        __half l1 = __float2half_rn(a1 - __half2float(h1));
        size_t idx = (size_t)(dt * 64 + d) * BSZ + bt * 64 + bp * 2;
        *(uint32_t*)((char*)g_xthi + idx * 2) = pk2h(h0, h1);
        *(uint32_t*)((char*)g_xtlo + idx * 2) = pk2h(l0, l1);
    }
}

// ============================================================
// Kernel 2: approx distance GEMM (hh-only fp16 HMMA) + top-2.
// Grid (32 b-groups, 4 j-quarters). CTA: 256 b x 4096 j.
// 16 warps = 4(wb: 64b) x 4(wj: 32j). W streamed 128j x 128k,
// double-buffered cp.async. wsq cached in SMEM.
// ============================================================
#define XS_STRIDE 528
#define OFF_WBUF  (256 * XS_STRIDE)          // 135168
#define WROW      272
#define WSTAGE    (128 * WROW)               // 34816
#define OFF_WSQ   (OFF_WBUF + 2 * WSTAGE)    // 204800
#define DIST_SMEM (OFF_WSQ + 16384)          // 221184

__device__ __forceinline__ void dist_prefetch(uint32_t sbase, int ci,
                                              int jbase, int tid) {
    int jt = ci >> 1, kc = ci & 1;
    uint32_t dbuf = sbase + OFF_WBUF + (uint32_t)(ci & 1) * WSTAGE;
    size_t gro = ((size_t)(jbase + jt * 128)) * KDIM + kc * 128;
#pragma unroll
    for (int t = 0; t < 4; t++) {
        int i = tid + 512 * t;               // 2048 16B segs
        int r = i >> 4, s = i & 15;
        cpa16(dbuf + r * WROW + s * 16,
              (const char*)(g_whi + gro + (size_t)r * KDIM) + s * 16);
    }
}

__global__ void __launch_bounds__(512, 1)
ker_dist_mma() {
    char* base = (char*)sm;
    uint32_t sbase = smem_u32(base);
    const int tid  = threadIdx.x;
    const int lane = tid & 31;
    const int wid  = tid >> 5;
    const int wb   = wid >> 2;        // 0..3 -> 64 b
    const int wj   = wid & 3;         // 0..3 -> 32 j
    const int g    = lane >> 2;
    const int c2   = (lane & 3) * 2;
    const int b0   = blockIdx.x * 256;
    const int quar = blockIdx.y;
    const int jbase = quar * 4096;

    const int la15 = lane & 15;
    const int laKA = (lane >> 4) << 4;
    const int laRB = (lane & 7) + ((lane >> 4) << 3);
    const int laKB = ((lane >> 3) & 1) << 4;

    // ---- load X tile (hi fp16, 256 rows x 512B) + wsq slice ----
#pragma unroll
    for (int t = 0; t < 16; t++) {
        int i = tid + 512 * t;               // 8192 segs
        int r = i >> 5, s = i & 31;
        *(uint4*)(base + r * XS_STRIDE + s * 16) =
            *(const uint4*)((const char*)(g_xhi + (size_t)(b0 + r) * KDIM) + s * 16);
    }
#pragma unroll
    for (int t = 0; t < 2; t++) {
        int i = tid + 512 * t;               // 1024 16B segs = 16KB
        *(uint4*)(base + OFF_WSQ + i * 16) =
            *(const uint4*)((const char*)(g_wsq + jbase) + i * 16);
    }
    const float* swsq = (const float*)(base + OFF_WSQ);

    float z1[8], z2[8];
    int   j1[8], j2[8];
#pragma unroll
    for (int i = 0; i < 8; i++) { z1[i] = z2[i] = FLT_MAX; j1[i] = j2[i] = MN; }

    dist_prefetch(sbase, 0, jbase, tid);
    CPA_COMMIT();

    float acc[4][4][4];

    for (int ci = 0; ci < 64; ci++) {
        const int jt = ci >> 1, kc = ci & 1;

        CPA_WAIT0();
        __syncthreads();
        if (ci + 1 < 64) {
            dist_prefetch(sbase, ci + 1, jbase, tid);
            CPA_COMMIT();
        }

        if (kc == 0) {
#pragma unroll
            for (int bt = 0; bt < 4; bt++)
#pragma unroll
                for (int nt = 0; nt < 4; nt++)
#pragma unroll
                    for (int r = 0; r < 4; r++) acc[bt][nt][r] = 0.f;
        }

        const uint32_t wboff = sbase + OFF_WBUF + (uint32_t)(ci & 1) * WSTAGE;
#pragma unroll
        for (int ks = 0; ks < 8; ks++) {
            uint32_t ah[4][4];
            const int kbX = (kc * 128 + ks * 16) * 2 + laKA;
#pragma unroll
            for (int bt = 0; bt < 4; bt++) {
                uint32_t ra = sbase + (wb * 64 + bt * 16 + la15) * XS_STRIDE + kbX;
                ldsm_x4(ah[bt][0], ah[bt][1], ah[bt][2], ah[bt][3], ra);
            }
            uint32_t bh[2][4];
            const int kbW = ks * 32 + laKB;
#pragma unroll
            for (int ntp = 0; ntp < 2; ntp++) {
                uint32_t rb = wboff + (wj * 32 + ntp * 16 + laRB) * WROW + kbW;
                ldsm_x4(bh[ntp][0], bh[ntp][1], bh[ntp][2], bh[ntp][3], rb);
            }
#pragma unroll
            for (int ntp = 0; ntp < 2; ntp++)
#pragma unroll
                for (int bt = 0; bt < 4; bt++) {
                    mma_f16(acc[bt][ntp*2],   ah[bt][0], ah[bt][1], ah[bt][2], ah[bt][3], bh[ntp][0], bh[ntp][1]);
                    mma_f16(acc[bt][ntp*2+1], ah[bt][0], ah[bt][1], ah[bt][2], ah[bt][3], bh[ntp][2], bh[ntp][3]);
                }
        }

        if (kc == 1) {
            const int j0 = jt * 128 + wj * 32;
#pragma unroll
            for (int nt = 0; nt < 4; nt++) {
                int jg = j0 + nt * 8 + c2;
                float w0 = swsq[jg];
                float w1 = swsq[jg + 1];
#pragma unroll
                for (int bt = 0; bt < 4; bt++) {
                    float za0 = fmaf(-2.f, acc[bt][nt][0], w0);
                    float zb0 = fmaf(-2.f, acc[bt][nt][1], w1);
                    float za1 = fmaf(-2.f, acc[bt][nt][2], w0);
                    float zb1 = fmaf(-2.f, acc[bt][nt][3], w1);
                    int s0 = bt * 2, s1 = bt * 2 + 1;
                    if (fminf(za0, zb0) < z2[s0]) {
                        t2_ins(za0, jg,     z1[s0], j1[s0], z2[s0], j2[s0]);
                        t2_ins(zb0, jg + 1, z1[s0], j1[s0], z2[s0], j2[s0]);
                    }
                    if (fminf(za1, zb1) < z2[s1]) {
                        t2_ins(za1, jg,     z1[s1], j1[s1], z2[s1], j2[s1]);
                        t2_ins(zb1, jg + 1, z1[s1], j1[s1], z2[s1], j2[s1]);
                    }
                }
            }
        }
    }

    // ---- cross-lane top-2 merge (c bits) ----
#pragma unroll
    for (int i = 0; i < 8; i++) {
#pragma unroll
        for (int off = 1; off <= 2; off <<= 1) {
            float oz1 = __shfl_xor_sync(0xffffffffu, z1[i], off);
            int   oj1 = __shfl_xor_sync(0xffffffffu, j1[i], off);
            float oz2 = __shfl_xor_sync(0xffffffffu, z2[i], off);
            int   oj2 = __shfl_xor_sync(0xffffffffu, j2[i], off);
            top2_merge(z1[i], j1[i], z2[i], j2[i], oz1, oj1, oz2, oj2);
        }
    }

    // ---- cross-warp top-2 merge via smem ----
    __syncthreads();
    float* sz1 = (float*)(base + OFF_WBUF);
    int*   sj1 = (int*)(base + OFF_WBUF + 4096);
    float* sz2 = (float*)(base + OFF_WBUF + 8192);
    int*   sj2 = (int*)(base + OFF_WBUF + 12288);
    if ((lane & 3) == 0) {
#pragma unroll
        for (int i = 0; i < 8; i++) {
            int bt = i >> 1, h = i & 1;
            int row = wb * 64 + bt * 16 + g + 8 * h;     // 0..255
            sz1[row * 4 + wj] = z1[i];
            sj1[row * 4 + wj] = j1[i];
            sz2[row * 4 + wj] = z2[i];
            sj2[row * 4 + wj] = j2[i];
        }
    }
    __syncthreads();
    if (tid < 256) {
        float a1 = sz1[tid * 4], a2 = sz2[tid * 4];
        int   i1 = sj1[tid * 4], i2 = sj2[tid * 4];
        for (int t = 1; t < 4; t++)
            top2_merge(a1, i1, a2, i2,
                       sz1[tid * 4 + t], sj1[tid * 4 + t],
                       sz2[tid * 4 + t], sj2[tid * 4 + t]);
        int gb = quar * BSZ + b0 + tid;
        g_cj[gb * 2]     = jbase + i1;
        g_cj[gb * 2 + 1] = jbase + i2;
    }
}

// ============================================================
// Kernel 2b: exact fp32 re-evaluation of <=8 BMU candidates.
// ============================================================
__global__ void ker_fix(const float* __restrict__ X,
                        const float* __restrict__ W) {
    int b    = blockIdx.x * 8 + (threadIdx.x >> 5);
    int lane = threadIdx.x & 31;

    int cand[8];
#pragma unroll
    for (int q = 0; q < 4; q++) {
        cand[q * 2]     = g_cj[((size_t)q * BSZ + b) * 2];
        cand[q * 2 + 1] = g_cj[((size_t)q * BSZ + b) * 2 + 1];
    }

    const float* xb = X + (size_t)b * KDIM;
    float x[8];
#pragma unroll
    for (int t = 0; t < 8; t++) x[t] = xb[lane * 8 + t];

    float bestz = FLT_MAX;
    int   bestj = MN;
#pragma unroll
    for (int c = 0; c < 8; c++) {
        int j = cand[c];
        const float* wj = W + (size_t)j * KDIM;
        float s = 0.f;
#pragma unroll
        for (int t = 0; t < 8; t++) s += x[t] * wj[lane * 8 + t];
#pragma unroll
        for (int o = 16; o > 0; o >>= 1) s += __shfl_down_sync(0xffffffffu, s, o);
        if (lane == 0) {
            float z = fmaf(-2.f, s, g_wsq[j]);
            if (z < bestz || (z == bestz && j < bestj)) { bestz = z; bestj = j; }
        }
    }
    if (lane == 0) g_bmu[b] = bestj;
}

// ============================================================
// Kernel 3: neighborhood factors (fp16) from exact BMU
// ============================================================
__global__ void ker_pxpy() {
    int i = blockIdx.x;
    float d  = g_sched[0];
    float lr = g_sched[1];
    float fi = (float)i;
    for (int b = threadIdx.x; b < BSZ; b += 256) {
        int bmu = g_bmu[b];
        float dr = fi - (float)(bmu >> 7);
        float dc = fi - (float)(bmu & 127);
        g_pxTh[(size_t)i * BSZ + b] = __float2half_rn(expf(-(dr * dr) / d));
        g_pyTh[(size_t)i * BSZ + b] = __float2half_rn(lr * expf(-(dc * dc) / d));
    }
}

// ============================================================
// Kernel 4: numer (fp16 HMMA, 2 terms) + fused denom.
// (unchanged from R11)
// ============================================================
#define N_ROW    144
#define N_ABUF   (128 * N_ROW)
#define N_XLO    (256 * N_ROW)
#define N_XBUF   (2 * N_XLO)
#define OFF_DSUM 0
#define OFF_A0   512
#define OFF_X0   (OFF_A0 + 2 * N_ABUF)
#define NUMER_SMEM (OFF_X0 + 2 * N_XBUF)     // 184832

__global__ void __launch_bounds__(512, 1)
ker_numer_tc(const float* __restrict__ Wold, float* __restrict__ OUT) {
    char* base = (char*)sm;
    uint32_t sbase = smem_u32(base);
    float* dsum = (float*)(base + OFF_DSUM);

    const int tid  = threadIdx.x;
    const int wid  = tid >> 5;
    const int lane = tid & 31;
    const int m    = blockIdx.x;

    const int n0 = (wid >> 2) * 32;
    const int d0 = (wid & 3) * 64;
    const int g  = lane >> 2;
    const int c2 = (lane & 3) * 2;

    const int la15 = lane & 15;
    const int laKA = (lane >> 4) << 4;
    const int laRB = (lane & 7) + ((lane >> 4) << 3);
    const int laKB = ((lane >> 3) & 1) << 4;

    if (tid < 128) dsum[tid] = 0.f;

    float acc[2][8][4];
#pragma unroll
    for (int mt = 0; mt < 2; mt++)
#pragma unroll
        for (int nt = 0; nt < 8; nt++)
#pragma unroll
            for (int r = 0; r < 4; r++) acc[mt][nt][r] = 0.f;

    const int bg = tid & 7;
    const int nrow = tid >> 3;
    float dden[2] = {0.f, 0.f};

#define NUMER_XPREF(ch) do {                                                   \
        int b0c = (ch) * 64;                                                   \
        uint32_t xb = sbase + OFF_X0 + (uint32_t)((ch) & 1) * N_XBUF;          \
        _Pragma("unroll")                                                      \
        for (int t = 0; t < 4; t++) {                                          \
            int i = tid + 512 * t;                                             \
            int r = i >> 3, s = i & 7;                                         \
            size_t go = ((size_t)r * BSZ + b0c + s * 8) * 2;                   \
            cpa16(xb + r * N_ROW + s * 16, (const char*)g_xthi + go);          \
            cpa16(xb + N_XLO + r * N_ROW + s * 16, (const char*)g_xtlo + go);  \
        }                                                                      \
    } while (0)

#define NUMER_LDG(ch, pxv, py0, py1) do {                                      \
        size_t bo = (size_t)((ch) * 64 + bg * 8) * 2;                          \
        pxv = *(const uint4*)((const char*)(g_pxTh + (size_t)m * BSZ) + bo);   \
        py0 = *(const uint4*)((const char*)(g_pyTh + (size_t)nrow * BSZ) + bo);\
        py1 = *(const uint4*)((const char*)(g_pyTh + (size_t)(nrow + 64) * BSZ) + bo); \
    } while (0)

#define NUMER_CONVERT(ch, pxv, py0, py1) do {                                  \
        uint32_t ab = (uint32_t)(OFF_A0 + ((ch) & 1) * N_ABUF);                \
        __half2* pxh = (__half2*)&(pxv);                                       \
        float2 pf[4];                                                          \
        _Pragma("unroll")                                                      \
        for (int k = 0; k < 4; k++) pf[k] = __half22float2(pxh[k]);            \
        _Pragma("unroll")                                                      \
        for (int s = 0; s < 2; s++) {                                          \
            int n = nrow + 64 * s;                                             \
            uint4 pv = s ? (py1) : (py0);                                      \
            __half2* ph = (__half2*)&pv;                                       \
            float ssum = 0.f;                                                  \
            __half h[8];                                                       \
            _Pragma("unroll")                                                  \
            for (int k = 0; k < 4; k++) {                                      \
                float2 yf = __half22float2(ph[k]);                             \
                float a0 = pf[k].x * yf.x;                                     \
                float a1 = pf[k].y * yf.y;                                     \
                h[2*k]   = __float2half_rn(a0);                                \
                h[2*k+1] = __float2half_rn(a1);                                \
                ssum += __half2float(h[2*k]) + __half2float(h[2*k+1]);         \
            }                                                                  \
            dden[s] += ssum;                                                   \
            uint4 hv = make_uint4(pk2h(h[0],h[1]), pk2h(h[2],h[3]),            \
                                  pk2h(h[4],h[5]), pk2h(h[6],h[7]));           \
            *(uint4*)(base + ab + n * N_ROW + bg * 16) = hv;                   \
        }                                                                      \
    } while (0)

    {
        uint4 pxv, py0, py1;
        NUMER_LDG(0, pxv, py0, py1);
        NUMER_CONVERT(0, pxv, py0, py1);
        NUMER_XPREF(0);
        CPA_COMMIT();
    }

    uint4 pxv, py0, py1;
    for (int ch = 0; ch < 128; ch++) {
        CPA_WAIT0();
        __syncthreads();

        const bool more = (ch + 1 < 128);
        if (more) {
            NUMER_XPREF(ch + 1);
            CPA_COMMIT();
            NUMER_LDG(ch + 1, pxv, py0, py1);
        }

        const uint32_t abase = sbase + OFF_A0 + (uint32_t)(ch & 1) * N_ABUF;
        const uint32_t xbase = sbase + OFF_X0 + (uint32_t)(ch & 1) * N_XBUF;
#pragma unroll
        for (int ks = 0; ks < 4; ks++) {
            uint32_t ah[2][4];
            const int kbA = ks * 32 + laKA;
#pragma unroll
            for (int bt = 0; bt < 2; bt++) {
                uint32_t ra = abase + (n0 + bt * 16 + la15) * N_ROW + kbA;
                ldsm_x4(ah[bt][0], ah[bt][1], ah[bt][2], ah[bt][3], ra);
            }
            const int kbB = ks * 32 + laKB;
#pragma unroll
            for (int h2 = 0; h2 < 2; h2++) {
                uint32_t bh[2][4], bl[2][4];
#pragma unroll
                for (int p = 0; p < 2; p++) {
                    int ntp = h2 * 2 + p;
                    uint32_t rb = xbase + (d0 + ntp * 16 + laRB) * N_ROW + kbB;
                    ldsm_x4(bh[p][0], bh[p][1], bh[p][2], bh[p][3], rb);
                    ldsm_x4(bl[p][0], bl[p][1], bl[p][2], bl[p][3], rb + N_XLO);
                }
#pragma unroll
                for (int p = 0; p < 2; p++)
#pragma unroll
                    for (int bt = 0; bt < 2; bt++) {
                        int nt = (h2 * 2 + p) * 2;
                        mma_f16(acc[bt][nt],   ah[bt][0], ah[bt][1], ah[bt][2], ah[bt][3], bh[p][0], bh[p][1]);
                        mma_f16(acc[bt][nt+1], ah[bt][0], ah[bt][1], ah[bt][2], ah[bt][3], bh[p][2], bh[p][3]);
                    }
#pragma unroll
                for (int p = 0; p < 2; p++)
#pragma unroll
                    for (int bt = 0; bt < 2; bt++) {
                        int nt = (h2 * 2 + p) * 2;
                        mma_f16(acc[bt][nt],   ah[bt][0], ah[bt][1], ah[bt][2], ah[bt][3], bl[p][0], bl[p][1]);
                        mma_f16(acc[bt][nt+1], ah[bt][0], ah[bt][1], ah[bt][2], ah[bt][3], bl[p][2], bl[p][3]);
                    }
            }
        }

        if (more) NUMER_CONVERT(ch + 1, pxv, py0, py1);
    }

    __syncthreads();
#pragma unroll
    for (int s = 0; s < 2; s++)
        atomicAdd(&dsum[nrow + 64 * s], dden[s]);
    __syncthreads();

#pragma unroll
    for (int mt = 0; mt < 2; mt++) {
#pragma unroll
        for (int gg = 0; gg < 2; gg++) {
            int n = n0 + mt * 16 + g + gg * 8;
            float den = dsum[n];
            size_t rb = ((size_t)(m * 128 + n)) * KDIM;
#pragma unroll
            for (int nt = 0; nt < 8; nt++) {
                int dcol = d0 + nt * 8 + c2;
                float v0 = acc[mt][nt][gg * 2];
                float v1 = acc[mt][nt][gg * 2 + 1];
                float2 o;
                if (den != 0.f) {
                    o.x = v0 / den; o.y = v1 / den;
                } else {
                    o.x = Wold[rb + dcol]; o.y = Wold[rb + dcol + 1];
                }
                *(float2*)(OUT + rb + dcol) = o;
            }
        }
    }
}

// ============================================================
extern "C" void kernel_launch(void* const* d_in, const int* in_sizes, int n_in,
                              void* d_out, int out_size) {
    (void)in_sizes; (void)n_in; (void)out_size;
    const float* data    = (const float*)d_in[0];
    const float* weights = (const float*)d_in[1];
    const int*   itp     = (const int*)d_in[2];
    float*       out     = (float*)d_out;

    cudaFuncSetAttribute(ker_dist_mma, cudaFuncAttributeMaxDynamicSharedMemorySize,
                         DIST_SMEM);
    cudaFuncSetAttribute(ker_numer_tc, cudaFuncAttributeMaxDynamicSharedMemorySize,
                         NUMER_SMEM);

    ker_sq<<<MN / 8, 256>>>(weights, itp);
    ker_split<<<(WPAIRS + XPAIRS) / 256, 256>>>(weights, data);
    ker_prep<<<dim3(BSZ / 64, KDIM / 64), 256>>>(data);
    ker_dist_mma<<<dim3(32, 4), 512, DIST_SMEM>>>();
    ker_fix<<<BSZ / 8, 256>>>(data, weights);
    ker_pxpy<<<128, 256>>>();
    ker_numer_tc<<<128, 512, NUMER_SMEM>>>(weights, out);
}